// round 1
// baseline (speedup 1.0000x reference)
#include <cuda_runtime.h>
#include <math.h>

#define BATCH 2
#define SEQ   1024
#define HID   1024
#define DI    2048
#define NST   16
#define KCONV 4
#define NLAYER 4
#define ROWS  (BATCH*SEQ)      // 2048
#define LN_EPS 1e-5f

// ---------------- scratch (device globals; no allocation) ----------------
__device__ float g_x  [ROWS*HID];      // running hidden (2048x1024)
__device__ float g_xn [ROWS*HID];      // layernorm output
__device__ float g_xr [ROWS*2*DI];     // in_proj output (2048x4096)
__device__ float g_xi [ROWS*DI];       // x_inner buf A
__device__ float g_xi2[ROWS*DI];       // x_inner buf B
__device__ float g_pr [ROWS*33];       // x_proj output
__device__ float g_y  [ROWS*DI];       // scan output
__device__ float g_t1 [ROWS*HID];      // MLP intermediate

// ---------------- helpers ----------------
__device__ __forceinline__ float siluf(float v) { return v / (1.f + expf(-v)); }
__device__ __forceinline__ float sigmoidf_(float v) { return 1.f / (1.f + expf(-v)); }
__device__ __forceinline__ float geluf(float v) { return 0.5f * v * (1.f + erff(v * 0.70710678118654752f)); }

// ---------------- LayerNorm (optional sigmoid-gate epilogue) ----------------
template<bool GATE>
__global__ void ln_kernel(const float* __restrict__ in,
                          const float* __restrict__ g,
                          const float* __restrict__ b,
                          const float* __restrict__ gate, int gateStride, int gateOff,
                          float* __restrict__ out, int cols)
{
    __shared__ float buf[2048];
    __shared__ float red[8];
    __shared__ float s_mu, s_rstd;
    const int row = blockIdx.x;
    const int tid = threadIdx.x;           // 256 threads
    const float* pin = in + (size_t)row * cols;

    float s = 0.f;
    for (int c = tid; c < cols; c += 256) { float v = pin[c]; buf[c] = v; s += v; }
    #pragma unroll
    for (int o = 16; o; o >>= 1) s += __shfl_xor_sync(0xffffffffu, s, o);
    if ((tid & 31) == 0) red[tid >> 5] = s;
    __syncthreads();
    if (tid == 0) {
        float t = 0.f;
        #pragma unroll
        for (int i = 0; i < 8; i++) t += red[i];
        s_mu = t / (float)cols;
    }
    __syncthreads();
    const float mu = s_mu;
    float v2 = 0.f;
    for (int c = tid; c < cols; c += 256) { float xc = buf[c] - mu; v2 += xc * xc; }
    #pragma unroll
    for (int o = 16; o; o >>= 1) v2 += __shfl_xor_sync(0xffffffffu, v2, o);
    __syncthreads();                        // protect red[] reuse
    if ((tid & 31) == 0) red[tid >> 5] = v2;
    __syncthreads();
    if (tid == 0) {
        float t = 0.f;
        #pragma unroll
        for (int i = 0; i < 8; i++) t += red[i];
        s_rstd = 1.f / sqrtf(t / (float)cols + LN_EPS);
    }
    __syncthreads();
    const float rstd = s_rstd;
    for (int c = tid; c < cols; c += 256) {
        float val = (buf[c] - mu) * rstd * g[c] + b[c];
        if (GATE) {
            float r = gate[(size_t)row * gateStride + gateOff + c];
            val *= sigmoidf_(r);
        }
        out[(size_t)row * cols + c] = val;
    }
}

// ---------------- tiled fp32 NT GEMM: C = A(MxK) * B(NxK)^T  ----------------
// EPI: 0 = C=acc ; 1 = C=resid+acc ; 2 = C=gelu(acc+bias) ; 3 = C=acc+bias+resid
#define GBM 128
#define GBN 128
#define GBK 16
template<int EPI>
__global__ void gemm_nt(const float* __restrict__ A, const float* __restrict__ Bw,
                        const float* __restrict__ bias, const float* __restrict__ resid,
                        float* __restrict__ C, int M, int N, int K)
{
    __shared__ float As[GBK][GBM + 4];
    __shared__ float Bs[GBK][GBN + 4];
    const int tid = threadIdx.x;            // 256
    const int tx = tid & 15;
    const int ty = tid >> 4;
    const int m0 = blockIdx.y * GBM;
    const int n0 = blockIdx.x * GBN;

    float acc[8][8];
    #pragma unroll
    for (int i = 0; i < 8; i++)
        #pragma unroll
        for (int j = 0; j < 8; j++) acc[i][j] = 0.f;

    for (int k0 = 0; k0 < K; k0 += GBK) {
        #pragma unroll
        for (int i = 0; i < 2; i++) {
            int v = tid + i * 256;          // 0..511 float4 slots
            int row = v >> 2;               // 0..127
            int c4 = (v & 3) * 4;           // 0,4,8,12
            float4 a = *reinterpret_cast<const float4*>(&A [(size_t)(m0 + row) * K + k0 + c4]);
            As[c4 + 0][row] = a.x; As[c4 + 1][row] = a.y;
            As[c4 + 2][row] = a.z; As[c4 + 3][row] = a.w;
            float4 bb = *reinterpret_cast<const float4*>(&Bw[(size_t)(n0 + row) * K + k0 + c4]);
            Bs[c4 + 0][row] = bb.x; Bs[c4 + 1][row] = bb.y;
            Bs[c4 + 2][row] = bb.z; Bs[c4 + 3][row] = bb.w;
        }
        __syncthreads();
        #pragma unroll
        for (int k = 0; k < GBK; k++) {
            float ar[8], br[8];
            #pragma unroll
            for (int i = 0; i < 8; i++) ar[i] = As[k][ty * 8 + i];
            #pragma unroll
            for (int j = 0; j < 8; j++) br[j] = Bs[k][tx * 8 + j];
            #pragma unroll
            for (int i = 0; i < 8; i++)
                #pragma unroll
                for (int j = 0; j < 8; j++)
                    acc[i][j] = fmaf(ar[i], br[j], acc[i][j]);
        }
        __syncthreads();
    }

    #pragma unroll
    for (int i = 0; i < 8; i++) {
        int m = m0 + ty * 8 + i;
        #pragma unroll
        for (int j = 0; j < 8; j++) {
            int n = n0 + tx * 8 + j;
            float v = acc[i][j];
            if (EPI == 1) v += resid[(size_t)m * N + n];
            if (EPI == 2) v = geluf(v + bias[n]);
            if (EPI == 3) v = v + bias[n] + resid[(size_t)m * N + n];
            C[(size_t)m * N + n] = v;
        }
    }
}

// ---------------- silu + split (take first DI cols of xr) ----------------
__global__ void silu_split(const float* __restrict__ xr, float* __restrict__ xi)
{
    int idx = blockIdx.x * blockDim.x + threadIdx.x;
    if (idx >= ROWS * DI) return;
    int row = idx / DI, d = idx % DI;
    xi[idx] = siluf(xr[(size_t)row * (2 * DI) + d]);
}

// ---------------- causal depthwise conv (K=4) + silu ----------------
__global__ void conv_kernel(const float* __restrict__ in, const float* __restrict__ w,
                            const float* __restrict__ bias, float* __restrict__ out)
{
    int idx = blockIdx.x * blockDim.x + threadIdx.x;
    if (idx >= ROWS * DI) return;
    int d = idx % DI;
    int s = (idx / DI) % SEQ;
    int b = idx / (DI * SEQ);
    float acc = bias[d];
    #pragma unroll
    for (int k = 0; k < KCONV; k++) {
        int t = s - (KCONV - 1) + k;
        if (t >= 0) acc = fmaf(in[((size_t)(b * SEQ + t)) * DI + d], w[d * KCONV + k], acc);
    }
    out[idx] = siluf(acc);
}

// ---------------- thin x_proj GEMM: proj(2048x33) = xi(2048x2048) * W(33x2048)^T --------
__global__ void xproj_kernel(const float* __restrict__ xi, const float* __restrict__ W,
                             float* __restrict__ proj)
{
    int gw = (blockIdx.x * blockDim.x + threadIdx.x) >> 5;
    int lane = threadIdx.x & 31;
    if (gw >= ROWS * 33) return;
    int row = gw / 33, p = gw % 33;
    const float* a = xi + (size_t)row * DI;
    const float* w = W + (size_t)p * DI;
    float acc = 0.f;
    for (int k = lane; k < DI; k += 32) acc = fmaf(a[k], w[k], acc);
    #pragma unroll
    for (int o = 16; o; o >>= 1) acc += __shfl_xor_sync(0xffffffffu, acc, o);
    if (lane == 0) proj[(size_t)row * 33 + p] = acc;
}

// ---------------- selective scan: 4 threads per channel, 4 states each ----------------
__global__ void scan_kernel(const float* __restrict__ xi, const float* __restrict__ proj,
                            const float* __restrict__ dtw, const float* __restrict__ dtb,
                            const float* __restrict__ Dv, float* __restrict__ y)
{
    int t = blockIdx.x * blockDim.x + threadIdx.x;   // over BATCH*DI*4
    int sub = t & 3;
    int gid = t >> 2;
    if (gid >= BATCH * DI) return;
    int b = gid / DI, d = gid % DI;
    const float w_dt = dtw[d];
    const float b_dt = dtb[d];
    const float Dd   = Dv[d];
    const float A0 = -(float)(sub * 4 + 1);
    const float A1 = -(float)(sub * 4 + 2);
    const float A2 = -(float)(sub * 4 + 3);
    const float A3 = -(float)(sub * 4 + 4);
    float h0 = 0.f, h1 = 0.f, h2 = 0.f, h3 = 0.f;

    for (int s = 0; s < SEQ; s++) {
        const float* pr = proj + (size_t)(b * SEQ + s) * 33;
        float dtraw = __ldg(&pr[0]);
        float z = fmaf(dtraw, w_dt, b_dt);
        float dt = (z > 20.f) ? z : log1pf(expf(z));
        float x = __ldg(&xi[(size_t)(b * SEQ + s) * DI + d]);
        float dtx = dt * x;

        float B0 = __ldg(&pr[1 + sub * 4 + 0]);
        float B1 = __ldg(&pr[1 + sub * 4 + 1]);
        float B2 = __ldg(&pr[1 + sub * 4 + 2]);
        float B3 = __ldg(&pr[1 + sub * 4 + 3]);
        float C0 = __ldg(&pr[17 + sub * 4 + 0]);
        float C1 = __ldg(&pr[17 + sub * 4 + 1]);
        float C2 = __ldg(&pr[17 + sub * 4 + 2]);
        float C3 = __ldg(&pr[17 + sub * 4 + 3]);

        float t0 = fmaf(h0, A0, dtx * B0); h0 = fmaf(dt, t0, h0);
        float t1 = fmaf(h1, A1, dtx * B1); h1 = fmaf(dt, t1, h1);
        float t2 = fmaf(h2, A2, dtx * B2); h2 = fmaf(dt, t2, h2);
        float t3 = fmaf(h3, A3, dtx * B3); h3 = fmaf(dt, t3, h3);

        float yp = h0 * C0;
        yp = fmaf(h1, C1, yp);
        yp = fmaf(h2, C2, yp);
        yp = fmaf(h3, C3, yp);
        yp += __shfl_xor_sync(0xffffffffu, yp, 1);
        yp += __shfl_xor_sync(0xffffffffu, yp, 2);
        if (sub == 0) y[(size_t)(b * SEQ + s) * DI + d] = fmaf(x, Dd, yp);
    }
}

// ---------------- host orchestration ----------------
extern "C" void kernel_launch(void* const* d_in, const int* in_sizes, int n_in,
                              void* d_out, int out_size)
{
    const float* hidden      = (const float*)d_in[0];
    const float* in_norm_g   = (const float*)d_in[1];
    const float* in_norm_b   = (const float*)d_in[2];
    const float* ln_g        = (const float*)d_in[3];
    const float* ln_b        = (const float*)d_in[4];
    const float* in_proj_w   = (const float*)d_in[5];
    const float* conv_w      = (const float*)d_in[6];
    const float* conv_b      = (const float*)d_in[7];
    const float* x_proj_w    = (const float*)d_in[8];
    const float* dt_proj_w   = (const float*)d_in[9];
    const float* dt_proj_b   = (const float*)d_in[10];
    const float* Dv          = (const float*)d_in[11];
    const float* mamba_ln_g  = (const float*)d_in[12];
    const float* mamba_ln_b  = (const float*)d_in[13];
    const float* out_proj_w  = (const float*)d_in[14];
    const float* op1_w       = (const float*)d_in[15];
    const float* op1_b       = (const float*)d_in[16];
    const float* op2_w       = (const float*)d_in[17];
    const float* op2_b       = (const float*)d_in[18];

    float *x, *xn, *xr, *xi, *xi2, *pr, *y, *t1;
    cudaGetSymbolAddress((void**)&x,   g_x);
    cudaGetSymbolAddress((void**)&xn,  g_xn);
    cudaGetSymbolAddress((void**)&xr,  g_xr);
    cudaGetSymbolAddress((void**)&xi,  g_xi);
    cudaGetSymbolAddress((void**)&xi2, g_xi2);
    cudaGetSymbolAddress((void**)&pr,  g_pr);
    cudaGetSymbolAddress((void**)&y,   g_y);
    cudaGetSymbolAddress((void**)&t1,  g_t1);

    const int elemDI = ROWS * DI;

    // x = LN(hidden)
    ln_kernel<false><<<ROWS, 256>>>(hidden, in_norm_g, in_norm_b, nullptr, 0, 0, x, HID);

    for (int l = 0; l < NLAYER; l++) {
        // xn = LN(x)
        ln_kernel<false><<<ROWS, 256>>>(x, ln_g + (size_t)l * HID, ln_b + (size_t)l * HID,
                                        nullptr, 0, 0, xn, HID);
        // xr = xn @ in_proj_w^T   (2048 x 4096)
        gemm_nt<0><<<dim3(2 * DI / GBN, ROWS / GBM), 256>>>(
            xn, in_proj_w + (size_t)l * 2 * DI * HID, nullptr, nullptr, xr, ROWS, 2 * DI, HID);
        // x_inner = silu(xr[:, :DI])
        silu_split<<<(elemDI + 255) / 256, 256>>>(xr, xi);
        // two causal dwconv + silu
        conv_kernel<<<(elemDI + 255) / 256, 256>>>(
            xi, conv_w + (size_t)(l * 2 + 0) * DI * KCONV, conv_b + (size_t)(l * 2 + 0) * DI, xi2);
        conv_kernel<<<(elemDI + 255) / 256, 256>>>(
            xi2, conv_w + (size_t)(l * 2 + 1) * DI * KCONV, conv_b + (size_t)(l * 2 + 1) * DI, xi);
        // proj = x_inner @ x_proj_w^T  (2048 x 33)
        xproj_kernel<<<(ROWS * 33 + 3) / 4, 128>>>(xi, x_proj_w + (size_t)l * 33 * DI, pr);
        // selective scan -> y (+ x_inner * D)
        scan_kernel<<<(BATCH * DI * 4) / 128, 128>>>(
            xi, pr, dt_proj_w + (size_t)l * DI, dt_proj_b + (size_t)l * DI,
            Dv + (size_t)l * DI, y);
        // y = LN(y) * sigmoid(res);  res = xr[:, DI:]
        ln_kernel<true><<<ROWS, 256>>>(y, mamba_ln_g + (size_t)l * DI, mamba_ln_b + (size_t)l * DI,
                                       xr, 2 * DI, DI, y, DI);
        // x = x + y @ out_proj_w^T
        gemm_nt<1><<<dim3(HID / GBN, ROWS / GBM), 256>>>(
            y, out_proj_w + (size_t)l * HID * DI, nullptr, x, x, ROWS, HID, DI);
    }

    // t1 = gelu(x @ op1_w^T + op1_b)
    gemm_nt<2><<<dim3(HID / GBN, ROWS / GBM), 256>>>(
        x, op1_w, op1_b, nullptr, t1, ROWS, HID, HID);
    // out = t1 @ op2_w^T + op2_b + hidden
    gemm_nt<3><<<dim3(HID / GBN, ROWS / GBM), 256>>>(
        t1, op2_w, op2_b, hidden, (float*)d_out, ROWS, HID, HID);
}

// round 2
// speedup vs baseline: 1.0065x; 1.0065x over previous
#include <cuda_runtime.h>
#include <math.h>

#define BATCH 2
#define SEQ   1024
#define HID   1024
#define DI    2048
#define NST   16
#define KCONV 4
#define NLAYER 4
#define ROWS  (BATCH*SEQ)      // 2048
#define LN_EPS 1e-5f

// ---------------- scratch (device globals; no allocation) ----------------
__device__ float g_x  [ROWS*HID];      // running hidden (2048x1024)
__device__ float g_xn [ROWS*HID];      // layernorm output
__device__ float g_xr [ROWS*2*DI];     // in_proj output (2048x4096)
__device__ float g_xi [ROWS*DI];       // x_inner buf A
__device__ float g_xi2[ROWS*DI];       // x_inner buf B
__device__ float g_pr [ROWS*33];       // x_proj output
__device__ float g_y  [ROWS*DI];       // scan output
__device__ float g_t1 [ROWS*HID];      // MLP intermediate

// ---------------- helpers ----------------
__device__ __forceinline__ float siluf(float v) { return v / (1.f + expf(-v)); }
__device__ __forceinline__ float sigmoidf_(float v) { return 1.f / (1.f + expf(-v)); }
__device__ __forceinline__ float geluf(float v) { return 0.5f * v * (1.f + erff(v * 0.70710678118654752f)); }

// ---------------- LayerNorm (optional sigmoid-gate epilogue) ----------------
template<bool GATE>
__global__ void ln_kernel(const float* __restrict__ in,
                          const float* __restrict__ g,
                          const float* __restrict__ b,
                          const float* __restrict__ gate, int gateStride, int gateOff,
                          float* __restrict__ out, int cols)
{
    __shared__ float buf[2048];
    __shared__ float red[8];
    __shared__ float s_mu, s_rstd;
    const int row = blockIdx.x;
    const int tid = threadIdx.x;           // 256 threads
    const float* pin = in + (size_t)row * cols;

    float s = 0.f;
    for (int c = tid; c < cols; c += 256) { float v = pin[c]; buf[c] = v; s += v; }
    #pragma unroll
    for (int o = 16; o; o >>= 1) s += __shfl_xor_sync(0xffffffffu, s, o);
    if ((tid & 31) == 0) red[tid >> 5] = s;
    __syncthreads();
    if (tid == 0) {
        float t = 0.f;
        #pragma unroll
        for (int i = 0; i < 8; i++) t += red[i];
        s_mu = t / (float)cols;
    }
    __syncthreads();
    const float mu = s_mu;
    float v2 = 0.f;
    for (int c = tid; c < cols; c += 256) { float xc = buf[c] - mu; v2 += xc * xc; }
    #pragma unroll
    for (int o = 16; o; o >>= 1) v2 += __shfl_xor_sync(0xffffffffu, v2, o);
    __syncthreads();                        // protect red[] reuse
    if ((tid & 31) == 0) red[tid >> 5] = v2;
    __syncthreads();
    if (tid == 0) {
        float t = 0.f;
        #pragma unroll
        for (int i = 0; i < 8; i++) t += red[i];
        s_rstd = 1.f / sqrtf(t / (float)cols + LN_EPS);
    }
    __syncthreads();
    const float rstd = s_rstd;
    for (int c = tid; c < cols; c += 256) {
        float val = (buf[c] - mu) * rstd * g[c] + b[c];
        if (GATE) {
            float r = gate[(size_t)row * gateStride + gateOff + c];
            val *= sigmoidf_(r);
        }
        out[(size_t)row * cols + c] = val;
    }
}

// ---------------- tiled fp32 NT GEMM: C = A(MxK) * B(NxK)^T  ----------------
// EPI: 0 = C=acc ; 1 = C=resid+acc ; 2 = C=gelu(acc+bias) ; 3 = C=acc+bias+resid
#define GBM 128
#define GBN 128
#define GBK 16
template<int EPI>
__global__ void gemm_nt(const float* __restrict__ A, const float* __restrict__ Bw,
                        const float* __restrict__ bias, const float* __restrict__ resid,
                        float* __restrict__ C, int M, int N, int K)
{
    __shared__ float As[GBK][GBM + 4];
    __shared__ float Bs[GBK][GBN + 4];
    const int tid = threadIdx.x;            // 256
    const int tx = tid & 15;
    const int ty = tid >> 4;
    const int m0 = blockIdx.y * GBM;
    const int n0 = blockIdx.x * GBN;

    float acc[8][8];
    #pragma unroll
    for (int i = 0; i < 8; i++)
        #pragma unroll
        for (int j = 0; j < 8; j++) acc[i][j] = 0.f;

    for (int k0 = 0; k0 < K; k0 += GBK) {
        #pragma unroll
        for (int i = 0; i < 2; i++) {
            int v = tid + i * 256;          // 0..511 float4 slots
            int row = v >> 2;               // 0..127
            int c4 = (v & 3) * 4;           // 0,4,8,12
            float4 a = *reinterpret_cast<const float4*>(&A [(size_t)(m0 + row) * K + k0 + c4]);
            As[c4 + 0][row] = a.x; As[c4 + 1][row] = a.y;
            As[c4 + 2][row] = a.z; As[c4 + 3][row] = a.w;
            float4 bb = *reinterpret_cast<const float4*>(&Bw[(size_t)(n0 + row) * K + k0 + c4]);
            Bs[c4 + 0][row] = bb.x; Bs[c4 + 1][row] = bb.y;
            Bs[c4 + 2][row] = bb.z; Bs[c4 + 3][row] = bb.w;
        }
        __syncthreads();
        #pragma unroll
        for (int k = 0; k < GBK; k++) {
            float ar[8], br[8];
            #pragma unroll
            for (int i = 0; i < 8; i++) ar[i] = As[k][ty * 8 + i];
            #pragma unroll
            for (int j = 0; j < 8; j++) br[j] = Bs[k][tx * 8 + j];
            #pragma unroll
            for (int i = 0; i < 8; i++)
                #pragma unroll
                for (int j = 0; j < 8; j++)
                    acc[i][j] = fmaf(ar[i], br[j], acc[i][j]);
        }
        __syncthreads();
    }

    #pragma unroll
    for (int i = 0; i < 8; i++) {
        int m = m0 + ty * 8 + i;
        #pragma unroll
        for (int j = 0; j < 8; j++) {
            int n = n0 + tx * 8 + j;
            float v = acc[i][j];
            if (EPI == 1) v += resid[(size_t)m * N + n];
            if (EPI == 2) v = geluf(v + bias[n]);
            if (EPI == 3) v = v + bias[n] + resid[(size_t)m * N + n];
            C[(size_t)m * N + n] = v;
        }
    }
}

// ---------------- silu + split (take first DI cols of xr) ----------------
__global__ void silu_split(const float* __restrict__ xr, float* __restrict__ xi)
{
    int idx = blockIdx.x * blockDim.x + threadIdx.x;
    if (idx >= ROWS * DI) return;
    int row = idx / DI, d = idx % DI;
    xi[idx] = siluf(xr[(size_t)row * (2 * DI) + d]);
}

// ---------------- causal depthwise conv (K=4) + silu ----------------
__global__ void conv_kernel(const float* __restrict__ in, const float* __restrict__ w,
                            const float* __restrict__ bias, float* __restrict__ out)
{
    int idx = blockIdx.x * blockDim.x + threadIdx.x;
    if (idx >= ROWS * DI) return;
    int d = idx % DI;
    int s = (idx / DI) % SEQ;
    int b = idx / (DI * SEQ);
    float acc = bias[d];
    #pragma unroll
    for (int k = 0; k < KCONV; k++) {
        int t = s - (KCONV - 1) + k;
        if (t >= 0) acc = fmaf(in[((size_t)(b * SEQ + t)) * DI + d], w[d * KCONV + k], acc);
    }
    out[idx] = siluf(acc);
}

// ---------------- thin x_proj GEMM: proj(2048x33) = xi(2048x2048) * W(33x2048)^T --------
__global__ void xproj_kernel(const float* __restrict__ xi, const float* __restrict__ W,
                             float* __restrict__ proj)
{
    int gw = (blockIdx.x * blockDim.x + threadIdx.x) >> 5;
    int lane = threadIdx.x & 31;
    if (gw >= ROWS * 33) return;
    int row = gw / 33, p = gw % 33;
    const float* a = xi + (size_t)row * DI;
    const float* w = W + (size_t)p * DI;
    float acc = 0.f;
    for (int k = lane; k < DI; k += 32) acc = fmaf(a[k], w[k], acc);
    #pragma unroll
    for (int o = 16; o; o >>= 1) acc += __shfl_xor_sync(0xffffffffu, acc, o);
    if (lane == 0) proj[(size_t)row * 33 + p] = acc;
}

// ---------------- selective scan: 4 threads per channel, 4 states each ----------------
__global__ void scan_kernel(const float* __restrict__ xi, const float* __restrict__ proj,
                            const float* __restrict__ dtw, const float* __restrict__ dtb,
                            const float* __restrict__ Dv, float* __restrict__ y)
{
    int t = blockIdx.x * blockDim.x + threadIdx.x;   // over BATCH*DI*4
    int sub = t & 3;
    int gid = t >> 2;
    if (gid >= BATCH * DI) return;
    int b = gid / DI, d = gid % DI;
    const float w_dt = dtw[d];
    const float b_dt = dtb[d];
    const float Dd   = Dv[d];
    const float A0 = -(float)(sub * 4 + 1);
    const float A1 = -(float)(sub * 4 + 2);
    const float A2 = -(float)(sub * 4 + 3);
    const float A3 = -(float)(sub * 4 + 4);
    float h0 = 0.f, h1 = 0.f, h2 = 0.f, h3 = 0.f;

    for (int s = 0; s < SEQ; s++) {
        const float* pr = proj + (size_t)(b * SEQ + s) * 33;
        float dtraw = __ldg(&pr[0]);
        float z = fmaf(dtraw, w_dt, b_dt);
        float dt = (z > 20.f) ? z : log1pf(expf(z));
        float x = __ldg(&xi[(size_t)(b * SEQ + s) * DI + d]);
        float dtx = dt * x;

        float B0 = __ldg(&pr[1 + sub * 4 + 0]);
        float B1 = __ldg(&pr[1 + sub * 4 + 1]);
        float B2 = __ldg(&pr[1 + sub * 4 + 2]);
        float B3 = __ldg(&pr[1 + sub * 4 + 3]);
        float C0 = __ldg(&pr[17 + sub * 4 + 0]);
        float C1 = __ldg(&pr[17 + sub * 4 + 1]);
        float C2 = __ldg(&pr[17 + sub * 4 + 2]);
        float C3 = __ldg(&pr[17 + sub * 4 + 3]);

        float t0 = fmaf(h0, A0, dtx * B0); h0 = fmaf(dt, t0, h0);
        float t1 = fmaf(h1, A1, dtx * B1); h1 = fmaf(dt, t1, h1);
        float t2 = fmaf(h2, A2, dtx * B2); h2 = fmaf(dt, t2, h2);
        float t3 = fmaf(h3, A3, dtx * B3); h3 = fmaf(dt, t3, h3);

        float yp = h0 * C0;
        yp = fmaf(h1, C1, yp);
        yp = fmaf(h2, C2, yp);
        yp = fmaf(h3, C3, yp);
        yp += __shfl_xor_sync(0xffffffffu, yp, 1);
        yp += __shfl_xor_sync(0xffffffffu, yp, 2);
        if (sub == 0) y[(size_t)(b * SEQ + s) * DI + d] = fmaf(x, Dd, yp);
    }
}

// ---------------- host orchestration ----------------
extern "C" void kernel_launch(void* const* d_in, const int* in_sizes, int n_in,
                              void* d_out, int out_size)
{
    const float* hidden      = (const float*)d_in[0];
    const float* in_norm_g   = (const float*)d_in[1];
    const float* in_norm_b   = (const float*)d_in[2];
    const float* ln_g        = (const float*)d_in[3];
    const float* ln_b        = (const float*)d_in[4];
    const float* in_proj_w   = (const float*)d_in[5];
    const float* conv_w      = (const float*)d_in[6];
    const float* conv_b      = (const float*)d_in[7];
    const float* x_proj_w    = (const float*)d_in[8];
    const float* dt_proj_w   = (const float*)d_in[9];
    const float* dt_proj_b   = (const float*)d_in[10];
    const float* Dv          = (const float*)d_in[11];
    const float* mamba_ln_g  = (const float*)d_in[12];
    const float* mamba_ln_b  = (const float*)d_in[13];
    const float* out_proj_w  = (const float*)d_in[14];
    const float* op1_w       = (const float*)d_in[15];
    const float* op1_b       = (const float*)d_in[16];
    const float* op2_w       = (const float*)d_in[17];
    const float* op2_b       = (const float*)d_in[18];

    float *x, *xn, *xr, *xi, *xi2, *pr, *y, *t1;
    cudaGetSymbolAddress((void**)&x,   g_x);
    cudaGetSymbolAddress((void**)&xn,  g_xn);
    cudaGetSymbolAddress((void**)&xr,  g_xr);
    cudaGetSymbolAddress((void**)&xi,  g_xi);
    cudaGetSymbolAddress((void**)&xi2, g_xi2);
    cudaGetSymbolAddress((void**)&pr,  g_pr);
    cudaGetSymbolAddress((void**)&y,   g_y);
    cudaGetSymbolAddress((void**)&t1,  g_t1);

    const int elemDI = ROWS * DI;

    // x = LN(hidden)
    ln_kernel<false><<<ROWS, 256>>>(hidden, in_norm_g, in_norm_b, nullptr, 0, 0, x, HID);

    for (int l = 0; l < NLAYER; l++) {
        // xn = LN(x)
        ln_kernel<false><<<ROWS, 256>>>(x, ln_g + (size_t)l * HID, ln_b + (size_t)l * HID,
                                        nullptr, 0, 0, xn, HID);
        // xr = xn @ in_proj_w^T   (2048 x 4096)
        gemm_nt<0><<<dim3(2 * DI / GBN, ROWS / GBM), 256>>>(
            xn, in_proj_w + (size_t)l * 2 * DI * HID, nullptr, nullptr, xr, ROWS, 2 * DI, HID);
        // x_inner = silu(xr[:, :DI])
        silu_split<<<(elemDI + 255) / 256, 256>>>(xr, xi);
        // two causal dwconv + silu
        conv_kernel<<<(elemDI + 255) / 256, 256>>>(
            xi, conv_w + (size_t)(l * 2 + 0) * DI * KCONV, conv_b + (size_t)(l * 2 + 0) * DI, xi2);
        conv_kernel<<<(elemDI + 255) / 256, 256>>>(
            xi2, conv_w + (size_t)(l * 2 + 1) * DI * KCONV, conv_b + (size_t)(l * 2 + 1) * DI, xi);
        // proj = x_inner @ x_proj_w^T  (2048 x 33)
        xproj_kernel<<<(ROWS * 33 + 3) / 4, 128>>>(xi, x_proj_w + (size_t)l * 33 * DI, pr);
        // selective scan -> y (+ x_inner * D)
        scan_kernel<<<(BATCH * DI * 4) / 128, 128>>>(
            xi, pr, dt_proj_w + (size_t)l * DI, dt_proj_b + (size_t)l * DI,
            Dv + (size_t)l * DI, y);
        // y = LN(y) * sigmoid(res);  res = xr[:, DI:]
        ln_kernel<true><<<ROWS, 256>>>(y, mamba_ln_g + (size_t)l * DI, mamba_ln_b + (size_t)l * DI,
                                       xr, 2 * DI, DI, y, DI);
        // x = x + y @ out_proj_w^T
        gemm_nt<1><<<dim3(HID / GBN, ROWS / GBM), 256>>>(
            y, out_proj_w + (size_t)l * HID * DI, nullptr, x, x, ROWS, HID, DI);
    }

    // t1 = gelu(x @ op1_w^T + op1_b)
    gemm_nt<2><<<dim3(HID / GBN, ROWS / GBM), 256>>>(
        x, op1_w, op1_b, nullptr, t1, ROWS, HID, HID);
    // out = t1 @ op2_w^T + op2_b + hidden
    gemm_nt<3><<<dim3(HID / GBN, ROWS / GBM), 256>>>(
        t1, op2_w, op2_b, hidden, (float*)d_out, ROWS, HID, HID);
}

// round 3
// speedup vs baseline: 1.5356x; 1.5258x over previous
#include <cuda_runtime.h>
#include <math.h>
#include <stdint.h>

#define BATCH 2
#define SEQ   1024
#define HID   1024
#define DI    2048
#define NST   16
#define KCONV 4
#define NLAYER 4
#define ROWS  (BATCH*SEQ)      // 2048
#define LN_EPS 1e-5f

// ---------------- scratch (device globals; no allocation) ----------------
__device__ float g_x  [ROWS*HID];      // running hidden
__device__ float g_xn [ROWS*HID];      // layernorm output
__device__ float g_res[ROWS*DI];       // gate half of in_proj
__device__ float g_xi [ROWS*DI];       // x_inner buf A
__device__ float g_xi2[ROWS*DI];       // x_inner buf B
__device__ float g_pr [ROWS*33];       // x_proj output
__device__ float g_y  [ROWS*DI];       // scan output
__device__ float g_t1 [ROWS*HID];      // MLP intermediate

// ---------------- helpers ----------------
__device__ __forceinline__ float siluf(float v) { return v / (1.f + expf(-v)); }
__device__ __forceinline__ float sigmoidf_(float v) { return 1.f / (1.f + expf(-v)); }
__device__ __forceinline__ float geluf(float v) { return 0.5f * v * (1.f + erff(v * 0.70710678118654752f)); }
__device__ __forceinline__ float to_tf32(float x) {
    uint32_t u;
    asm("cvt.rna.tf32.f32 %0, %1;" : "=r"(u) : "f"(x));
    return __uint_as_float(u);
}

// ---------------- LayerNorm (optional sigmoid-gate epilogue) ----------------
template<bool GATE>
__global__ void ln_kernel(const float* __restrict__ in,
                          const float* __restrict__ g,
                          const float* __restrict__ b,
                          const float* __restrict__ gate,
                          float* __restrict__ out, int cols)
{
    __shared__ float buf[2048];
    __shared__ float red[8];
    __shared__ float s_mu, s_rstd;
    const int row = blockIdx.x;
    const int tid = threadIdx.x;           // 256 threads
    const float* pin = in + (size_t)row * cols;

    float s = 0.f;
    for (int c = tid; c < cols; c += 256) { float v = pin[c]; buf[c] = v; s += v; }
    #pragma unroll
    for (int o = 16; o; o >>= 1) s += __shfl_xor_sync(0xffffffffu, s, o);
    if ((tid & 31) == 0) red[tid >> 5] = s;
    __syncthreads();
    if (tid == 0) {
        float t = 0.f;
        #pragma unroll
        for (int i = 0; i < 8; i++) t += red[i];
        s_mu = t / (float)cols;
    }
    __syncthreads();
    const float mu = s_mu;
    float v2 = 0.f;
    for (int c = tid; c < cols; c += 256) { float xc = buf[c] - mu; v2 += xc * xc; }
    #pragma unroll
    for (int o = 16; o; o >>= 1) v2 += __shfl_xor_sync(0xffffffffu, v2, o);
    __syncthreads();
    if ((tid & 31) == 0) red[tid >> 5] = v2;
    __syncthreads();
    if (tid == 0) {
        float t = 0.f;
        #pragma unroll
        for (int i = 0; i < 8; i++) t += red[i];
        s_rstd = 1.f / sqrtf(t / (float)cols + LN_EPS);
    }
    __syncthreads();
    const float rstd = s_rstd;
    for (int c = tid; c < cols; c += 256) {
        float val = (buf[c] - mu) * rstd * g[c] + b[c];
        if (GATE) val *= sigmoidf_(gate[(size_t)row * cols + c]);
        out[(size_t)row * cols + c] = val;
    }
}

// ---------------- tf32 tensor-core NT GEMM: C = A(MxK) * B(NxK)^T ----------------
// EPI: 0 plain ; 1 +resid ; 2 gelu(acc+bias) ; 3 acc+bias+resid ;
//      4 in_proj split: n<DI -> C[m*DI+n]=silu(acc), else resid[m*DI+n-DI]=acc
#define BM 128
#define BN 128
#define BKT 32
#define SKEW 4

template<int EPI>
__global__ __launch_bounds__(256, 2)
void gemm_tf32(const float* __restrict__ A, const float* __restrict__ Bw,
               const float* __restrict__ bias, float* __restrict__ resid,
               float* __restrict__ C, int M, int N, int K)
{
    __shared__ float As[BM][BKT + SKEW];
    __shared__ float Bs[BN][BKT + SKEW];

    const int tid  = threadIdx.x;          // 256
    const int lane = tid & 31;
    const int w    = tid >> 5;             // 8 warps
    const int wm   = w & 1;                // 2 warps in M (64 rows each)
    const int wn   = w >> 1;               // 4 warps in N (32 cols each)
    const int m0 = blockIdx.y * BM;
    const int n0 = blockIdx.x * BN;
    const int lq = lane >> 2;              // 0..7
    const int lr = lane & 3;               // 0..3

    float acc[4][4][4];
    #pragma unroll
    for (int i = 0; i < 4; i++)
        #pragma unroll
        for (int j = 0; j < 4; j++)
            #pragma unroll
            for (int r = 0; r < 4; r++) acc[i][j][r] = 0.f;

    for (int k0 = 0; k0 < K; k0 += BKT) {
        // load 128x32 tiles of A and B (8 float4 per row), convert to tf32
        #pragma unroll
        for (int i = 0; i < 4; i++) {
            int slot = tid + i * 256;      // 0..1023
            int row  = slot >> 3;
            int c4   = (slot & 7) * 4;
            float4 a = *reinterpret_cast<const float4*>(&A [(size_t)(m0 + row) * K + k0 + c4]);
            a.x = to_tf32(a.x); a.y = to_tf32(a.y); a.z = to_tf32(a.z); a.w = to_tf32(a.w);
            *reinterpret_cast<float4*>(&As[row][c4]) = a;
            float4 b = *reinterpret_cast<const float4*>(&Bw[(size_t)(n0 + row) * K + k0 + c4]);
            b.x = to_tf32(b.x); b.y = to_tf32(b.y); b.z = to_tf32(b.z); b.w = to_tf32(b.w);
            *reinterpret_cast<float4*>(&Bs[row][c4]) = b;
        }
        __syncthreads();

        #pragma unroll
        for (int kk = 0; kk < BKT; kk += 8) {
            uint32_t afr[4][4], bfr[4][2];
            #pragma unroll
            for (int mt = 0; mt < 4; mt++) {
                int r = wm * 64 + mt * 16 + lq;
                afr[mt][0] = __float_as_uint(As[r    ][kk     + lr]);
                afr[mt][1] = __float_as_uint(As[r + 8][kk     + lr]);
                afr[mt][2] = __float_as_uint(As[r    ][kk + 4 + lr]);
                afr[mt][3] = __float_as_uint(As[r + 8][kk + 4 + lr]);
            }
            #pragma unroll
            for (int nt = 0; nt < 4; nt++) {
                int rn = wn * 32 + nt * 8 + lq;
                bfr[nt][0] = __float_as_uint(Bs[rn][kk     + lr]);
                bfr[nt][1] = __float_as_uint(Bs[rn][kk + 4 + lr]);
            }
            #pragma unroll
            for (int mt = 0; mt < 4; mt++)
                #pragma unroll
                for (int nt = 0; nt < 4; nt++) {
                    asm volatile(
                        "mma.sync.aligned.m16n8k8.row.col.f32.tf32.tf32.f32 "
                        "{%0,%1,%2,%3}, {%4,%5,%6,%7}, {%8,%9}, {%0,%1,%2,%3};"
                        : "+f"(acc[mt][nt][0]), "+f"(acc[mt][nt][1]),
                          "+f"(acc[mt][nt][2]), "+f"(acc[mt][nt][3])
                        : "r"(afr[mt][0]), "r"(afr[mt][1]), "r"(afr[mt][2]), "r"(afr[mt][3]),
                          "r"(bfr[nt][0]), "r"(bfr[nt][1]));
                }
        }
        __syncthreads();
    }

    // epilogue
    #pragma unroll
    for (int mt = 0; mt < 4; mt++) {
        #pragma unroll
        for (int nt = 0; nt < 4; nt++) {
            int r0 = m0 + wm * 64 + mt * 16 + lq;
            int c  = n0 + wn * 32 + nt * 8 + lr * 2;
            #pragma unroll
            for (int half = 0; half < 2; half++) {
                int m = r0 + half * 8;
                float v0 = acc[mt][nt][half * 2 + 0];
                float v1 = acc[mt][nt][half * 2 + 1];
                if (EPI == 0) {
                    *reinterpret_cast<float2*>(&C[(size_t)m * N + c]) = make_float2(v0, v1);
                } else if (EPI == 1) {
                    float2 rr = *reinterpret_cast<const float2*>(&resid[(size_t)m * N + c]);
                    *reinterpret_cast<float2*>(&C[(size_t)m * N + c]) = make_float2(v0 + rr.x, v1 + rr.y);
                } else if (EPI == 2) {
                    *reinterpret_cast<float2*>(&C[(size_t)m * N + c]) =
                        make_float2(geluf(v0 + bias[c]), geluf(v1 + bias[c + 1]));
                } else if (EPI == 3) {
                    float2 rr = *reinterpret_cast<const float2*>(&resid[(size_t)m * N + c]);
                    *reinterpret_cast<float2*>(&C[(size_t)m * N + c]) =
                        make_float2(v0 + bias[c] + rr.x, v1 + bias[c + 1] + rr.y);
                } else { // EPI == 4 (in_proj split), tile columns never straddle DI
                    if (c < DI)
                        *reinterpret_cast<float2*>(&C[(size_t)m * DI + c]) =
                            make_float2(siluf(v0), siluf(v1));
                    else
                        *reinterpret_cast<float2*>(&resid[(size_t)m * DI + c - DI]) =
                            make_float2(v0, v1);
                }
            }
        }
    }
}

// ---------------- causal depthwise conv (K=4) + silu ----------------
__global__ void conv_kernel(const float* __restrict__ in, const float* __restrict__ w,
                            const float* __restrict__ bias, float* __restrict__ out)
{
    int idx = blockIdx.x * blockDim.x + threadIdx.x;
    if (idx >= ROWS * DI) return;
    int d = idx % DI;
    int s = (idx / DI) % SEQ;
    int b = idx / (DI * SEQ);
    float acc = bias[d];
    #pragma unroll
    for (int k = 0; k < KCONV; k++) {
        int t = s - (KCONV - 1) + k;
        if (t >= 0) acc = fmaf(in[((size_t)(b * SEQ + t)) * DI + d], w[d * KCONV + k], acc);
    }
    out[idx] = siluf(acc);
}

// ---------------- thin x_proj GEMM (N=33, warp-per-dot) ----------------
__global__ void xproj_kernel(const float* __restrict__ xi, const float* __restrict__ W,
                             float* __restrict__ proj)
{
    int gw = (blockIdx.x * blockDim.x + threadIdx.x) >> 5;
    int lane = threadIdx.x & 31;
    if (gw >= ROWS * 33) return;
    int row = gw / 33, p = gw % 33;
    const float* a = xi + (size_t)row * DI;
    const float* w = W + (size_t)p * DI;
    float acc = 0.f;
    for (int k = lane; k < DI; k += 32) acc = fmaf(a[k], w[k], acc);
    #pragma unroll
    for (int o = 16; o; o >>= 1) acc += __shfl_xor_sync(0xffffffffu, acc, o);
    if (lane == 0) proj[(size_t)row * 33 + p] = acc;
}

// ---------------- selective scan: 4 threads per channel, 4 states each ----------------
__global__ void scan_kernel(const float* __restrict__ xi, const float* __restrict__ proj,
                            const float* __restrict__ dtw, const float* __restrict__ dtb,
                            const float* __restrict__ Dv, float* __restrict__ y)
{
    int t = blockIdx.x * blockDim.x + threadIdx.x;   // over BATCH*DI*4
    int sub = t & 3;
    int gid = t >> 2;
    if (gid >= BATCH * DI) return;
    int b = gid / DI, d = gid % DI;
    const float w_dt = dtw[d];
    const float b_dt = dtb[d];
    const float Dd   = Dv[d];
    const float A0 = -(float)(sub * 4 + 1);
    const float A1 = -(float)(sub * 4 + 2);
    const float A2 = -(float)(sub * 4 + 3);
    const float A3 = -(float)(sub * 4 + 4);
    float h0 = 0.f, h1 = 0.f, h2 = 0.f, h3 = 0.f;

    for (int s = 0; s < SEQ; s++) {
        const float* pr = proj + (size_t)(b * SEQ + s) * 33;
        float dtraw = __ldg(&pr[0]);
        float z = fmaf(dtraw, w_dt, b_dt);
        float dt = (z > 20.f) ? z : log1pf(expf(z));
        float x = __ldg(&xi[(size_t)(b * SEQ + s) * DI + d]);
        float dtx = dt * x;

        float B0 = __ldg(&pr[1 + sub * 4 + 0]);
        float B1 = __ldg(&pr[1 + sub * 4 + 1]);
        float B2 = __ldg(&pr[1 + sub * 4 + 2]);
        float B3 = __ldg(&pr[1 + sub * 4 + 3]);
        float C0 = __ldg(&pr[17 + sub * 4 + 0]);
        float C1 = __ldg(&pr[17 + sub * 4 + 1]);
        float C2 = __ldg(&pr[17 + sub * 4 + 2]);
        float C3 = __ldg(&pr[17 + sub * 4 + 3]);

        float t0 = fmaf(h0, A0, dtx * B0); h0 = fmaf(dt, t0, h0);
        float t1 = fmaf(h1, A1, dtx * B1); h1 = fmaf(dt, t1, h1);
        float t2 = fmaf(h2, A2, dtx * B2); h2 = fmaf(dt, t2, h2);
        float t3 = fmaf(h3, A3, dtx * B3); h3 = fmaf(dt, t3, h3);

        float yp = h0 * C0;
        yp = fmaf(h1, C1, yp);
        yp = fmaf(h2, C2, yp);
        yp = fmaf(h3, C3, yp);
        yp += __shfl_xor_sync(0xffffffffu, yp, 1);
        yp += __shfl_xor_sync(0xffffffffu, yp, 2);
        if (sub == 0) y[(size_t)(b * SEQ + s) * DI + d] = fmaf(x, Dd, yp);
    }
}

// ---------------- host orchestration ----------------
extern "C" void kernel_launch(void* const* d_in, const int* in_sizes, int n_in,
                              void* d_out, int out_size)
{
    const float* hidden      = (const float*)d_in[0];
    const float* in_norm_g   = (const float*)d_in[1];
    const float* in_norm_b   = (const float*)d_in[2];
    const float* ln_g        = (const float*)d_in[3];
    const float* ln_b        = (const float*)d_in[4];
    const float* in_proj_w   = (const float*)d_in[5];
    const float* conv_w      = (const float*)d_in[6];
    const float* conv_b      = (const float*)d_in[7];
    const float* x_proj_w    = (const float*)d_in[8];
    const float* dt_proj_w   = (const float*)d_in[9];
    const float* dt_proj_b   = (const float*)d_in[10];
    const float* Dv          = (const float*)d_in[11];
    const float* mamba_ln_g  = (const float*)d_in[12];
    const float* mamba_ln_b  = (const float*)d_in[13];
    const float* out_proj_w  = (const float*)d_in[14];
    const float* op1_w       = (const float*)d_in[15];
    const float* op1_b       = (const float*)d_in[16];
    const float* op2_w       = (const float*)d_in[17];
    const float* op2_b       = (const float*)d_in[18];

    float *x, *xn, *res, *xi, *xi2, *pr, *y, *t1;
    cudaGetSymbolAddress((void**)&x,   g_x);
    cudaGetSymbolAddress((void**)&xn,  g_xn);
    cudaGetSymbolAddress((void**)&res, g_res);
    cudaGetSymbolAddress((void**)&xi,  g_xi);
    cudaGetSymbolAddress((void**)&xi2, g_xi2);
    cudaGetSymbolAddress((void**)&pr,  g_pr);
    cudaGetSymbolAddress((void**)&y,   g_y);
    cudaGetSymbolAddress((void**)&t1,  g_t1);

    const int elemDI = ROWS * DI;

    // x = LN(hidden)
    ln_kernel<false><<<ROWS, 256>>>(hidden, in_norm_g, in_norm_b, nullptr, x, HID);

    for (int l = 0; l < NLAYER; l++) {
        // xn = LN(x)
        ln_kernel<false><<<ROWS, 256>>>(x, ln_g + (size_t)l * HID, ln_b + (size_t)l * HID,
                                        nullptr, xn, HID);
        // in_proj: xi = silu(first half), res = second half   (2048 x 4096 x 1024)
        gemm_tf32<4><<<dim3(2 * DI / BN, ROWS / BM), 256>>>(
            xn, in_proj_w + (size_t)l * 2 * DI * HID, nullptr, res, xi, ROWS, 2 * DI, HID);
        // two causal dwconv + silu
        conv_kernel<<<(elemDI + 255) / 256, 256>>>(
            xi, conv_w + (size_t)(l * 2 + 0) * DI * KCONV, conv_b + (size_t)(l * 2 + 0) * DI, xi2);
        conv_kernel<<<(elemDI + 255) / 256, 256>>>(
            xi2, conv_w + (size_t)(l * 2 + 1) * DI * KCONV, conv_b + (size_t)(l * 2 + 1) * DI, xi);
        // proj = x_inner @ x_proj_w^T  (2048 x 33)
        xproj_kernel<<<(ROWS * 33 + 3) / 4, 128>>>(xi, x_proj_w + (size_t)l * 33 * DI, pr);
        // selective scan -> y (+ x_inner * D)
        scan_kernel<<<(BATCH * DI * 4) / 128, 128>>>(
            xi, pr, dt_proj_w + (size_t)l * DI, dt_proj_b + (size_t)l * DI,
            Dv + (size_t)l * DI, y);
        // y = LN(y) * sigmoid(res)
        ln_kernel<true><<<ROWS, 256>>>(y, mamba_ln_g + (size_t)l * DI, mamba_ln_b + (size_t)l * DI,
                                       res, y, DI);
        // x = x + y @ out_proj_w^T   (2048 x 1024 x 2048)
        gemm_tf32<1><<<dim3(HID / BN, ROWS / BM), 256>>>(
            y, out_proj_w + (size_t)l * HID * DI, nullptr, x, x, ROWS, HID, DI);
    }

    // t1 = gelu(x @ op1_w^T + op1_b)
    gemm_tf32<2><<<dim3(HID / BN, ROWS / BM), 256>>>(
        x, op1_w, op1_b, nullptr, t1, ROWS, HID, HID);
    // out = t1 @ op2_w^T + op2_b + hidden
    gemm_tf32<3><<<dim3(HID / BN, ROWS / BM), 256>>>(
        t1, op2_w, op2_b, (float*)hidden, (float*)d_out, ROWS, HID, HID);
}

// round 5
// speedup vs baseline: 1.6239x; 1.0575x over previous
#include <cuda_runtime.h>
#include <math.h>
#include <stdint.h>

#define BATCH 2
#define SEQ   1024
#define HID   1024
#define DI    2048
#define NST   16
#define KCONV 4
#define NLAYER 4
#define ROWS  (BATCH*SEQ)      // 2048
#define LN_EPS 1e-5f

// ---------------- scratch (device globals; no allocation) ----------------
__device__ float g_x  [ROWS*HID];
__device__ float g_xn [ROWS*HID];
__device__ float g_res[ROWS*DI];
__device__ float g_xi [ROWS*DI];
__device__ float g_xi2[ROWS*DI];
__device__ float g_pr [ROWS*33];
__device__ float g_y  [ROWS*DI];
__device__ float g_t1 [ROWS*HID];

// ---------------- helpers ----------------
__device__ __forceinline__ float siluf(float v) { return v / (1.f + expf(-v)); }
__device__ __forceinline__ float sigmoidf_(float v) { return 1.f / (1.f + expf(-v)); }
__device__ __forceinline__ float geluf(float v) { return 0.5f * v * (1.f + erff(v * 0.70710678118654752f)); }

__device__ __forceinline__ uint32_t smem_u32(const void* p) {
    uint32_t a;
    asm("{ .reg .u64 t; cvta.to.shared.u64 t, %1; cvt.u32.u64 %0, t; }" : "=r"(a) : "l"(p));
    return a;
}
__device__ __forceinline__ void cp16(uint32_t d, const void* g) {
    asm volatile("cp.async.cg.shared.global [%0], [%1], 16;" :: "r"(d), "l"(g));
}

// ---------------- LayerNorm (optional sigmoid-gate epilogue) ----------------
template<bool GATE>
__global__ void ln_kernel(const float* __restrict__ in,
                          const float* __restrict__ g,
                          const float* __restrict__ b,
                          const float* __restrict__ gate,
                          float* __restrict__ out, int cols)
{
    __shared__ float buf[2048];
    __shared__ float red[8];
    __shared__ float s_mu, s_rstd;
    const int row = blockIdx.x;
    const int tid = threadIdx.x;
    const float* pin = in + (size_t)row * cols;

    float s = 0.f;
    for (int c = tid; c < cols; c += 256) { float v = pin[c]; buf[c] = v; s += v; }
    #pragma unroll
    for (int o = 16; o; o >>= 1) s += __shfl_xor_sync(0xffffffffu, s, o);
    if ((tid & 31) == 0) red[tid >> 5] = s;
    __syncthreads();
    if (tid == 0) {
        float t = 0.f;
        #pragma unroll
        for (int i = 0; i < 8; i++) t += red[i];
        s_mu = t / (float)cols;
    }
    __syncthreads();
    const float mu = s_mu;
    float v2 = 0.f;
    for (int c = tid; c < cols; c += 256) { float xc = buf[c] - mu; v2 += xc * xc; }
    #pragma unroll
    for (int o = 16; o; o >>= 1) v2 += __shfl_xor_sync(0xffffffffu, v2, o);
    __syncthreads();
    if ((tid & 31) == 0) red[tid >> 5] = v2;
    __syncthreads();
    if (tid == 0) {
        float t = 0.f;
        #pragma unroll
        for (int i = 0; i < 8; i++) t += red[i];
        s_rstd = 1.f / sqrtf(t / (float)cols + LN_EPS);
    }
    __syncthreads();
    const float rstd = s_rstd;
    for (int c = tid; c < cols; c += 256) {
        float val = (buf[c] - mu) * rstd * g[c] + b[c];
        if (GATE) val *= sigmoidf_(gate[(size_t)row * cols + c]);
        out[(size_t)row * cols + c] = val;
    }
}

// ---------------- tf32 mma.sync GEMM with cp.async double buffering ----------------
// C = A(MxK) * B(NxK)^T, 128 x TBN tile per CTA, BK=32, 2-stage pipeline.
// EPI: 0 plain ; 1 +resid ; 2 gelu(acc+bias) ; 3 acc+bias+resid ;
//      4 in_proj split: n<DI -> C=silu(acc), else resid[...]=acc
#define SKEWF 36                     // floats per smem row (32 + 4 skew); 144B, 16B-aligned

template<int EPI, int TBN>
__global__ __launch_bounds__(256, 2)
void gemm_mma(const float* __restrict__ A, const float* __restrict__ Bw,
              const float* __restrict__ bias, float* __restrict__ resid,
              float* __restrict__ C, int M, int N, int K)
{
    constexpr int NT   = TBN / 32;           // n8-tiles per warp (4 or 2)
    constexpr int WNC  = TBN / 4;            // cols per warp (32 or 16)
    constexpr int ASTG = 128 * SKEWF;        // floats per A stage
    constexpr int BSTG = TBN * SKEWF;        // floats per B stage
    constexpr int STG  = ASTG + BSTG;
    extern __shared__ float sm[];            // 2 stages

    const int tid  = threadIdx.x;            // 256
    const int lane = tid & 31;
    const int w    = tid >> 5;
    const int wm   = w & 1;                  // 2 warps in M
    const int wn   = w >> 1;                 // 4 warps in N
    const int m0 = blockIdx.y * 128;
    const int n0 = blockIdx.x * TBN;
    const int lq = lane >> 2;
    const int lr = lane & 3;

    float acc[4][NT][4];
    #pragma unroll
    for (int i = 0; i < 4; i++)
        #pragma unroll
        for (int j = 0; j < NT; j++)
            #pragma unroll
            for (int r = 0; r < 4; r++) acc[i][j][r] = 0.f;

    const int NC = K >> 5;

    // stage loader
    auto load_stage = [&](int s, int k0) {
        float* dA = sm + s * STG;
        float* dB = dA + ASTG;
        #pragma unroll
        for (int i = 0; i < 4; i++) {                     // A: 1024 float4 slots
            int slot = tid + i * 256;
            int row = slot >> 3, c4 = (slot & 7) * 4;
            cp16(smem_u32(dA + row * SKEWF + c4), A + (size_t)(m0 + row) * K + k0 + c4);
        }
        #pragma unroll
        for (int i = 0; i < TBN * 8 / 256; i++) {         // B: TBN*8 slots
            int slot = tid + i * 256;
            int row = slot >> 3, c4 = (slot & 7) * 4;
            cp16(smem_u32(dB + row * SKEWF + c4), Bw + (size_t)(n0 + row) * K + k0 + c4);
        }
        asm volatile("cp.async.commit_group;" ::: "memory");
    };

    load_stage(0, 0);

    for (int c = 0; c < NC; c++) {
        const int s = c & 1;
        if (c + 1 < NC) {
            load_stage(s ^ 1, (c + 1) * 32);
            asm volatile("cp.async.wait_group 1;" ::: "memory");
        } else {
            asm volatile("cp.async.wait_group 0;" ::: "memory");
        }
        __syncthreads();

        const float* sA = sm + s * STG;
        const float* sB = sA + ASTG;
        #pragma unroll
        for (int kk = 0; kk < 32; kk += 8) {
            uint32_t afr[4][4], bfr[NT][2];
            #pragma unroll
            for (int mt = 0; mt < 4; mt++) {
                int r = wm * 64 + mt * 16 + lq;
                afr[mt][0] = __float_as_uint(sA[(r    ) * SKEWF + kk     + lr]);
                afr[mt][1] = __float_as_uint(sA[(r + 8) * SKEWF + kk     + lr]);
                afr[mt][2] = __float_as_uint(sA[(r    ) * SKEWF + kk + 4 + lr]);
                afr[mt][3] = __float_as_uint(sA[(r + 8) * SKEWF + kk + 4 + lr]);
            }
            #pragma unroll
            for (int nt = 0; nt < NT; nt++) {
                int rn = wn * WNC + nt * 8 + lq;
                bfr[nt][0] = __float_as_uint(sB[rn * SKEWF + kk     + lr]);
                bfr[nt][1] = __float_as_uint(sB[rn * SKEWF + kk + 4 + lr]);
            }
            #pragma unroll
            for (int mt = 0; mt < 4; mt++)
                #pragma unroll
                for (int nt = 0; nt < NT; nt++) {
                    asm volatile(
                        "mma.sync.aligned.m16n8k8.row.col.f32.tf32.tf32.f32 "
                        "{%0,%1,%2,%3}, {%4,%5,%6,%7}, {%8,%9}, {%0,%1,%2,%3};"
                        : "+f"(acc[mt][nt][0]), "+f"(acc[mt][nt][1]),
                          "+f"(acc[mt][nt][2]), "+f"(acc[mt][nt][3])
                        : "r"(afr[mt][0]), "r"(afr[mt][1]), "r"(afr[mt][2]), "r"(afr[mt][3]),
                          "r"(bfr[nt][0]), "r"(bfr[nt][1]));
                }
        }
        __syncthreads();
    }

    // epilogue
    #pragma unroll
    for (int mt = 0; mt < 4; mt++) {
        #pragma unroll
        for (int nt = 0; nt < NT; nt++) {
            int r0 = m0 + wm * 64 + mt * 16 + lq;
            int cc = n0 + wn * WNC + nt * 8 + lr * 2;
            #pragma unroll
            for (int half = 0; half < 2; half++) {
                int m = r0 + half * 8;
                float v0 = acc[mt][nt][half * 2 + 0];
                float v1 = acc[mt][nt][half * 2 + 1];
                if (EPI == 0) {
                    *reinterpret_cast<float2*>(&C[(size_t)m * N + cc]) = make_float2(v0, v1);
                } else if (EPI == 1) {
                    float2 rr = *reinterpret_cast<const float2*>(&resid[(size_t)m * N + cc]);
                    *reinterpret_cast<float2*>(&C[(size_t)m * N + cc]) = make_float2(v0 + rr.x, v1 + rr.y);
                } else if (EPI == 2) {
                    *reinterpret_cast<float2*>(&C[(size_t)m * N + cc]) =
                        make_float2(geluf(v0 + bias[cc]), geluf(v1 + bias[cc + 1]));
                } else if (EPI == 3) {
                    float2 rr = *reinterpret_cast<const float2*>(&resid[(size_t)m * N + cc]);
                    *reinterpret_cast<float2*>(&C[(size_t)m * N + cc]) =
                        make_float2(v0 + bias[cc] + rr.x, v1 + bias[cc + 1] + rr.y);
                } else {                           // EPI 4: in_proj split (tiles never straddle DI)
                    if (cc < DI)
                        *reinterpret_cast<float2*>(&C[(size_t)m * DI + cc]) =
                            make_float2(siluf(v0), siluf(v1));
                    else
                        *reinterpret_cast<float2*>(&resid[(size_t)m * DI + cc - DI]) =
                            make_float2(v0, v1);
                }
            }
        }
    }
}

// ---------------- fused double causal dwconv (K=4) + silu ----------------
// out = silu(conv2(silu(conv1(in))))  with zero padding of each stage's input.
#define CCHUNK 64
__global__ void conv2_kernel(const float* __restrict__ in,
                             const float* __restrict__ w1, const float* __restrict__ b1,
                             const float* __restrict__ w2, const float* __restrict__ b2,
                             float* __restrict__ out)
{
    int idx = blockIdx.x * blockDim.x + threadIdx.x;
    if (idx >= BATCH * DI * (SEQ / CCHUNK)) return;
    int d  = idx % DI;
    int r  = idx / DI;
    int c0 = r % (SEQ / CCHUNK);
    int b  = r / (SEQ / CCHUNK);
    int t0 = c0 * CCHUNK;

    const float wa0 = w1[d*4+0], wa1 = w1[d*4+1], wa2 = w1[d*4+2], wa3 = w1[d*4+3];
    const float wb0 = w2[d*4+0], wb1 = w2[d*4+1], wb2 = w2[d*4+2], wb3 = w2[d*4+3];
    const float bb1 = b1[d], bb2 = b2[d];
    const float* pin  = in  + (size_t)b * SEQ * DI + d;
    float*       pout = out + (size_t)b * SEQ * DI + d;

    // conv1+silu history for t = t0-3 .. t0-1 (zero for t<0)
    float h[3];
    #pragma unroll
    for (int j = 0; j < 3; j++) {
        int t = t0 - 3 + j;
        if (t >= 0) {
            float a = bb1;
            float wv[4] = {wa0, wa1, wa2, wa3};
            #pragma unroll
            for (int k = 0; k < 4; k++) {
                int tt = t - 3 + k;
                if (tt >= 0) a = fmaf(pin[(size_t)tt * DI], wv[k], a);
            }
            h[j] = siluf(a);
        } else h[j] = 0.f;
    }
    // rolling input window
    float xm3 = (t0 - 3 >= 0) ? pin[(size_t)(t0 - 3) * DI] : 0.f;
    float xm2 = (t0 - 2 >= 0) ? pin[(size_t)(t0 - 2) * DI] : 0.f;
    float xm1 = (t0 - 1 >= 0) ? pin[(size_t)(t0 - 1) * DI] : 0.f;

    for (int t = t0; t < t0 + CCHUNK; t++) {
        float xt = pin[(size_t)t * DI];
        float v1 = bb1;
        v1 = fmaf(wa0, xm3, v1); v1 = fmaf(wa1, xm2, v1);
        v1 = fmaf(wa2, xm1, v1); v1 = fmaf(wa3, xt,  v1);
        float s = siluf(v1);
        float v2 = bb2;
        v2 = fmaf(wb0, h[0], v2); v2 = fmaf(wb1, h[1], v2);
        v2 = fmaf(wb2, h[2], v2); v2 = fmaf(wb3, s,    v2);
        pout[(size_t)t * DI] = siluf(v2);
        xm3 = xm2; xm2 = xm1; xm1 = xt;
        h[0] = h[1]; h[1] = h[2]; h[2] = s;
    }
}

// ---------------- thin x_proj GEMM (N=33, warp-per-dot) ----------------
__global__ void xproj_kernel(const float* __restrict__ xi, const float* __restrict__ W,
                             float* __restrict__ proj)
{
    int gw = (blockIdx.x * blockDim.x + threadIdx.x) >> 5;
    int lane = threadIdx.x & 31;
    if (gw >= ROWS * 33) return;
    int row = gw / 33, p = gw % 33;
    const float* a = xi + (size_t)row * DI;
    const float* w = W + (size_t)p * DI;
    float acc = 0.f;
    for (int k = lane; k < DI; k += 32) acc = fmaf(a[k], w[k], acc);
    #pragma unroll
    for (int o = 16; o; o >>= 1) acc += __shfl_xor_sync(0xffffffffu, acc, o);
    if (lane == 0) proj[(size_t)row * 33 + p] = acc;
}

// ---------------- selective scan ----------------
__global__ void scan_kernel(const float* __restrict__ xi, const float* __restrict__ proj,
                            const float* __restrict__ dtw, const float* __restrict__ dtb,
                            const float* __restrict__ Dv, float* __restrict__ y)
{
    int t = blockIdx.x * blockDim.x + threadIdx.x;
    int sub = t & 3;
    int gid = t >> 2;
    if (gid >= BATCH * DI) return;
    int b = gid / DI, d = gid % DI;
    const float w_dt = dtw[d];
    const float b_dt = dtb[d];
    const float Dd   = Dv[d];
    const float A0 = -(float)(sub * 4 + 1);
    const float A1 = -(float)(sub * 4 + 2);
    const float A2 = -(float)(sub * 4 + 3);
    const float A3 = -(float)(sub * 4 + 4);
    float h0 = 0.f, h1 = 0.f, h2 = 0.f, h3 = 0.f;

    for (int s = 0; s < SEQ; s++) {
        const float* pr = proj + (size_t)(b * SEQ + s) * 33;
        float dtraw = __ldg(&pr[0]);
        float z = fmaf(dtraw, w_dt, b_dt);
        float dt = (z > 20.f) ? z : log1pf(expf(z));
        float x = __ldg(&xi[(size_t)(b * SEQ + s) * DI + d]);
        float dtx = dt * x;

        float B0 = __ldg(&pr[1 + sub * 4 + 0]);
        float B1 = __ldg(&pr[1 + sub * 4 + 1]);
        float B2 = __ldg(&pr[1 + sub * 4 + 2]);
        float B3 = __ldg(&pr[1 + sub * 4 + 3]);
        float C0 = __ldg(&pr[17 + sub * 4 + 0]);
        float C1 = __ldg(&pr[17 + sub * 4 + 1]);
        float C2 = __ldg(&pr[17 + sub * 4 + 2]);
        float C3 = __ldg(&pr[17 + sub * 4 + 3]);

        float t0 = fmaf(h0, A0, dtx * B0); h0 = fmaf(dt, t0, h0);
        float t1 = fmaf(h1, A1, dtx * B1); h1 = fmaf(dt, t1, h1);
        float t2 = fmaf(h2, A2, dtx * B2); h2 = fmaf(dt, t2, h2);
        float t3 = fmaf(h3, A3, dtx * B3); h3 = fmaf(dt, t3, h3);

        float yp = h0 * C0;
        yp = fmaf(h1, C1, yp);
        yp = fmaf(h2, C2, yp);
        yp = fmaf(h3, C3, yp);
        yp += __shfl_xor_sync(0xffffffffu, yp, 1);
        yp += __shfl_xor_sync(0xffffffffu, yp, 2);
        if (sub == 0) y[(size_t)(b * SEQ + s) * DI + d] = fmaf(x, Dd, yp);
    }
}

// ---------------- host orchestration ----------------
#define SMEM128 (2 * (128*SKEWF + 128*SKEWF) * 4)
#define SMEM64  (2 * (128*SKEWF +  64*SKEWF) * 4)

extern "C" void kernel_launch(void* const* d_in, const int* in_sizes, int n_in,
                              void* d_out, int out_size)
{
    const float* hidden      = (const float*)d_in[0];
    const float* in_norm_g   = (const float*)d_in[1];
    const float* in_norm_b   = (const float*)d_in[2];
    const float* ln_g        = (const float*)d_in[3];
    const float* ln_b        = (const float*)d_in[4];
    const float* in_proj_w   = (const float*)d_in[5];
    const float* conv_w      = (const float*)d_in[6];
    const float* conv_b      = (const float*)d_in[7];
    const float* x_proj_w    = (const float*)d_in[8];
    const float* dt_proj_w   = (const float*)d_in[9];
    const float* dt_proj_b   = (const float*)d_in[10];
    const float* Dv          = (const float*)d_in[11];
    const float* mamba_ln_g  = (const float*)d_in[12];
    const float* mamba_ln_b  = (const float*)d_in[13];
    const float* out_proj_w  = (const float*)d_in[14];
    const float* op1_w       = (const float*)d_in[15];
    const float* op1_b       = (const float*)d_in[16];
    const float* op2_w       = (const float*)d_in[17];
    const float* op2_b       = (const float*)d_in[18];

    float *x, *xn, *res, *xi, *xi2, *pr, *y, *t1;
    cudaGetSymbolAddress((void**)&x,   g_x);
    cudaGetSymbolAddress((void**)&xn,  g_xn);
    cudaGetSymbolAddress((void**)&res, g_res);
    cudaGetSymbolAddress((void**)&xi,  g_xi);
    cudaGetSymbolAddress((void**)&xi2, g_xi2);
    cudaGetSymbolAddress((void**)&pr,  g_pr);
    cudaGetSymbolAddress((void**)&y,   g_y);
    cudaGetSymbolAddress((void**)&t1,  g_t1);

    cudaFuncSetAttribute(gemm_mma<4,128>, cudaFuncAttributeMaxDynamicSharedMemorySize, SMEM128);
    cudaFuncSetAttribute(gemm_mma<1,64>,  cudaFuncAttributeMaxDynamicSharedMemorySize, SMEM64);
    cudaFuncSetAttribute(gemm_mma<2,64>,  cudaFuncAttributeMaxDynamicSharedMemorySize, SMEM64);
    cudaFuncSetAttribute(gemm_mma<3,64>,  cudaFuncAttributeMaxDynamicSharedMemorySize, SMEM64);

    // x = LN(hidden)
    ln_kernel<false><<<ROWS, 256>>>(hidden, in_norm_g, in_norm_b, nullptr, x, HID);

    for (int l = 0; l < NLAYER; l++) {
        // xn = LN(x)
        ln_kernel<false><<<ROWS, 256>>>(x, ln_g + (size_t)l * HID, ln_b + (size_t)l * HID,
                                        nullptr, xn, HID);
        // in_proj: xi = silu(first half), res = second half  (2048 x 4096 x 1024)
        gemm_mma<4,128><<<dim3(2 * DI / 128, ROWS / 128), 256, SMEM128>>>(
            xn, in_proj_w + (size_t)l * 2 * DI * HID, nullptr, res, xi, ROWS, 2 * DI, HID);
        // fused conv1+silu+conv2+silu : xi -> xi2
        conv2_kernel<<<(BATCH * DI * (SEQ / CCHUNK)) / 256, 256>>>(
            xi,
            conv_w + (size_t)(l * 2 + 0) * DI * KCONV, conv_b + (size_t)(l * 2 + 0) * DI,
            conv_w + (size_t)(l * 2 + 1) * DI * KCONV, conv_b + (size_t)(l * 2 + 1) * DI,
            xi2);
        // proj = x_inner @ x_proj_w^T  (2048 x 33)
        xproj_kernel<<<(ROWS * 33 + 3) / 4, 128>>>(xi2, x_proj_w + (size_t)l * 33 * DI, pr);
        // selective scan -> y (+ x_inner * D)
        scan_kernel<<<(BATCH * DI * 4) / 128, 128>>>(
            xi2, pr, dt_proj_w + (size_t)l * DI, dt_proj_b + (size_t)l * DI,
            Dv + (size_t)l * DI, y);
        // y = LN(y) * sigmoid(res)
        ln_kernel<true><<<ROWS, 256>>>(y, mamba_ln_g + (size_t)l * DI, mamba_ln_b + (size_t)l * DI,
                                       res, y, DI);
        // x = x + y @ out_proj_w^T  (2048 x 1024 x 2048)
        gemm_mma<1,64><<<dim3(HID / 64, ROWS / 128), 256, SMEM64>>>(
            y, out_proj_w + (size_t)l * HID * DI, nullptr, x, x, ROWS, HID, DI);
    }

    // t1 = gelu(x @ op1_w^T + op1_b)
    gemm_mma<2,64><<<dim3(HID / 64, ROWS / 128), 256, SMEM64>>>(
        x, op1_w, op1_b, nullptr, t1, ROWS, HID, HID);
    // out = t1 @ op2_w^T + op2_b + hidden
    gemm_mma<3,64><<<dim3(HID / 64, ROWS / 128), 256, SMEM64>>>(
        t1, op2_w, op2_b, (float*)hidden, (float*)d_out, ROWS, HID, HID);
}

// round 6
// speedup vs baseline: 1.8875x; 1.1623x over previous
#include <cuda_runtime.h>
#include <math.h>
#include <stdint.h>

#define BATCH 2
#define SEQ   1024
#define HID   1024
#define DI    2048
#define NST   16
#define KCONV 4
#define NLAYER 4
#define ROWS  (BATCH*SEQ)      // 2048
#define LN_EPS 1e-5f

// ---------------- scratch (device globals; no allocation) ----------------
__device__ float g_x  [ROWS*HID];
__device__ float g_xn [ROWS*HID];
__device__ float g_res[ROWS*DI];
__device__ float g_xi [ROWS*DI];
__device__ float g_xi2[ROWS*DI];
__device__ float g_pr [ROWS*33];
__device__ float g_y  [ROWS*DI];
__device__ float g_t1 [ROWS*HID];
__device__ float g_wt [NLAYER*DI*34];   // transposed x_proj weights

// ---------------- helpers ----------------
__device__ __forceinline__ float siluf(float v) { return v / (1.f + expf(-v)); }
__device__ __forceinline__ float sigmoidf_(float v) { return 1.f / (1.f + expf(-v)); }
__device__ __forceinline__ float geluf(float v) { return 0.5f * v * (1.f + erff(v * 0.70710678118654752f)); }
__device__ __forceinline__ uint32_t to_tf32u(float x) {
    uint32_t u;
    asm("cvt.rna.tf32.f32 %0, %1;" : "=r"(u) : "f"(x));
    return u;
}
__device__ __forceinline__ uint32_t smem_u32(const void* p) {
    uint32_t a;
    asm("{ .reg .u64 t; cvta.to.shared.u64 t, %1; cvt.u32.u64 %0, t; }" : "=r"(a) : "l"(p));
    return a;
}
__device__ __forceinline__ void cp16(uint32_t d, const void* g) {
    asm volatile("cp.async.cg.shared.global [%0], [%1], 16;" :: "r"(d), "l"(g));
}

// ---------------- LayerNorm (optional sigmoid-gate epilogue) ----------------
template<bool GATE>
__global__ void ln_kernel(const float* __restrict__ in,
                          const float* __restrict__ g,
                          const float* __restrict__ b,
                          const float* __restrict__ gate,
                          float* __restrict__ out, int cols)
{
    __shared__ float buf[2048];
    __shared__ float red[8];
    __shared__ float s_mu, s_rstd;
    const int row = blockIdx.x;
    const int tid = threadIdx.x;
    const float* pin = in + (size_t)row * cols;

    float s = 0.f;
    for (int c = tid; c < cols; c += 256) { float v = pin[c]; buf[c] = v; s += v; }
    #pragma unroll
    for (int o = 16; o; o >>= 1) s += __shfl_xor_sync(0xffffffffu, s, o);
    if ((tid & 31) == 0) red[tid >> 5] = s;
    __syncthreads();
    if (tid == 0) {
        float t = 0.f;
        #pragma unroll
        for (int i = 0; i < 8; i++) t += red[i];
        s_mu = t / (float)cols;
    }
    __syncthreads();
    const float mu = s_mu;
    float v2 = 0.f;
    for (int c = tid; c < cols; c += 256) { float xc = buf[c] - mu; v2 += xc * xc; }
    #pragma unroll
    for (int o = 16; o; o >>= 1) v2 += __shfl_xor_sync(0xffffffffu, v2, o);
    __syncthreads();
    if ((tid & 31) == 0) red[tid >> 5] = v2;
    __syncthreads();
    if (tid == 0) {
        float t = 0.f;
        #pragma unroll
        for (int i = 0; i < 8; i++) t += red[i];
        s_rstd = 1.f / sqrtf(t / (float)cols + LN_EPS);
    }
    __syncthreads();
    const float rstd = s_rstd;
    for (int c = tid; c < cols; c += 256) {
        float val = (buf[c] - mu) * rstd * g[c] + b[c];
        if (GATE) val *= sigmoidf_(gate[(size_t)row * cols + c]);
        out[(size_t)row * cols + c] = val;
    }
}

// ---------------- tf32 mma.sync GEMM, cp.async double-buffered ----------------
// C = A(MxK) * B(NxK)^T, 128 x TBN tile, BK=32, rna-rounded fragments.
// EPI: 0 plain ; 1 +resid ; 2 gelu(acc+bias) ; 3 acc+bias+resid ; 5 silu(acc)
#define SKEWF 36

template<int EPI, int TBN>
__global__ __launch_bounds__(256, 2)
void gemm_mma(const float* __restrict__ A, const float* __restrict__ Bw,
              const float* __restrict__ bias, float* __restrict__ resid,
              float* __restrict__ C, int M, int N, int K)
{
    constexpr int NT   = TBN / 32;
    constexpr int WNC  = TBN / 4;
    constexpr int ASTG = 128 * SKEWF;
    constexpr int BSTG = TBN * SKEWF;
    constexpr int STG  = ASTG + BSTG;
    extern __shared__ float sm[];

    const int tid  = threadIdx.x;
    const int lane = tid & 31;
    const int w    = tid >> 5;
    const int wm   = w & 1;
    const int wn   = w >> 1;
    const int m0 = blockIdx.y * 128;
    const int n0 = blockIdx.x * TBN;
    const int lq = lane >> 2;
    const int lr = lane & 3;

    float acc[4][NT][4];
    #pragma unroll
    for (int i = 0; i < 4; i++)
        #pragma unroll
        for (int j = 0; j < NT; j++)
            #pragma unroll
            for (int r = 0; r < 4; r++) acc[i][j][r] = 0.f;

    const int NC = K >> 5;

    auto load_stage = [&](int s, int k0) {
        float* dA = sm + s * STG;
        float* dB = dA + ASTG;
        #pragma unroll
        for (int i = 0; i < 4; i++) {
            int slot = tid + i * 256;
            int row = slot >> 3, c4 = (slot & 7) * 4;
            cp16(smem_u32(dA + row * SKEWF + c4), A + (size_t)(m0 + row) * K + k0 + c4);
        }
        #pragma unroll
        for (int i = 0; i < TBN * 8 / 256; i++) {
            int slot = tid + i * 256;
            int row = slot >> 3, c4 = (slot & 7) * 4;
            cp16(smem_u32(dB + row * SKEWF + c4), Bw + (size_t)(n0 + row) * K + k0 + c4);
        }
        asm volatile("cp.async.commit_group;" ::: "memory");
    };

    load_stage(0, 0);

    for (int c = 0; c < NC; c++) {
        const int s = c & 1;
        if (c + 1 < NC) {
            load_stage(s ^ 1, (c + 1) * 32);
            asm volatile("cp.async.wait_group 1;" ::: "memory");
        } else {
            asm volatile("cp.async.wait_group 0;" ::: "memory");
        }
        __syncthreads();

        const float* sA = sm + s * STG;
        const float* sB = sA + ASTG;
        #pragma unroll
        for (int kk = 0; kk < 32; kk += 8) {
            uint32_t afr[4][4], bfr[NT][2];
            #pragma unroll
            for (int mt = 0; mt < 4; mt++) {
                int r = wm * 64 + mt * 16 + lq;
                afr[mt][0] = to_tf32u(sA[(r    ) * SKEWF + kk     + lr]);
                afr[mt][1] = to_tf32u(sA[(r + 8) * SKEWF + kk     + lr]);
                afr[mt][2] = to_tf32u(sA[(r    ) * SKEWF + kk + 4 + lr]);
                afr[mt][3] = to_tf32u(sA[(r + 8) * SKEWF + kk + 4 + lr]);
            }
            #pragma unroll
            for (int nt = 0; nt < NT; nt++) {
                int rn = wn * WNC + nt * 8 + lq;
                bfr[nt][0] = to_tf32u(sB[rn * SKEWF + kk     + lr]);
                bfr[nt][1] = to_tf32u(sB[rn * SKEWF + kk + 4 + lr]);
            }
            #pragma unroll
            for (int mt = 0; mt < 4; mt++)
                #pragma unroll
                for (int nt = 0; nt < NT; nt++) {
                    asm volatile(
                        "mma.sync.aligned.m16n8k8.row.col.f32.tf32.tf32.f32 "
                        "{%0,%1,%2,%3}, {%4,%5,%6,%7}, {%8,%9}, {%0,%1,%2,%3};"
                        : "+f"(acc[mt][nt][0]), "+f"(acc[mt][nt][1]),
                          "+f"(acc[mt][nt][2]), "+f"(acc[mt][nt][3])
                        : "r"(afr[mt][0]), "r"(afr[mt][1]), "r"(afr[mt][2]), "r"(afr[mt][3]),
                          "r"(bfr[nt][0]), "r"(bfr[nt][1]));
                }
        }
        __syncthreads();
    }

    #pragma unroll
    for (int mt = 0; mt < 4; mt++) {
        #pragma unroll
        for (int nt = 0; nt < NT; nt++) {
            int r0 = m0 + wm * 64 + mt * 16 + lq;
            int cc = n0 + wn * WNC + nt * 8 + lr * 2;
            #pragma unroll
            for (int half = 0; half < 2; half++) {
                int m = r0 + half * 8;
                float v0 = acc[mt][nt][half * 2 + 0];
                float v1 = acc[mt][nt][half * 2 + 1];
                if (EPI == 0) {
                    *reinterpret_cast<float2*>(&C[(size_t)m * N + cc]) = make_float2(v0, v1);
                } else if (EPI == 1) {
                    float2 rr = *reinterpret_cast<const float2*>(&resid[(size_t)m * N + cc]);
                    *reinterpret_cast<float2*>(&C[(size_t)m * N + cc]) = make_float2(v0 + rr.x, v1 + rr.y);
                } else if (EPI == 2) {
                    *reinterpret_cast<float2*>(&C[(size_t)m * N + cc]) =
                        make_float2(geluf(v0 + bias[cc]), geluf(v1 + bias[cc + 1]));
                } else if (EPI == 3) {
                    float2 rr = *reinterpret_cast<const float2*>(&resid[(size_t)m * N + cc]);
                    *reinterpret_cast<float2*>(&C[(size_t)m * N + cc]) =
                        make_float2(v0 + bias[cc] + rr.x, v1 + bias[cc + 1] + rr.y);
                } else if (EPI == 5) {
                    *reinterpret_cast<float2*>(&C[(size_t)m * N + cc]) =
                        make_float2(siluf(v0), siluf(v1));
                }
            }
        }
    }
}

// ---------------- fused double causal dwconv (K=4) + silu ----------------
#define CCHUNK 16
__global__ void conv2_kernel(const float* __restrict__ in,
                             const float* __restrict__ w1, const float* __restrict__ b1,
                             const float* __restrict__ w2, const float* __restrict__ b2,
                             float* __restrict__ out)
{
    int idx = blockIdx.x * blockDim.x + threadIdx.x;
    if (idx >= BATCH * DI * (SEQ / CCHUNK)) return;
    int d  = idx % DI;
    int r  = idx / DI;
    int c0 = r % (SEQ / CCHUNK);
    int b  = r / (SEQ / CCHUNK);
    int t0 = c0 * CCHUNK;

    const float wa0 = w1[d*4+0], wa1 = w1[d*4+1], wa2 = w1[d*4+2], wa3 = w1[d*4+3];
    const float wb0 = w2[d*4+0], wb1 = w2[d*4+1], wb2 = w2[d*4+2], wb3 = w2[d*4+3];
    const float bb1 = b1[d], bb2 = b2[d];
    const float* pin  = in  + (size_t)b * SEQ * DI + d;
    float*       pout = out + (size_t)b * SEQ * DI + d;

    float h[3];
    #pragma unroll
    for (int j = 0; j < 3; j++) {
        int t = t0 - 3 + j;
        if (t >= 0) {
            float a = bb1;
            float wv[4] = {wa0, wa1, wa2, wa3};
            #pragma unroll
            for (int k = 0; k < 4; k++) {
                int tt = t - 3 + k;
                if (tt >= 0) a = fmaf(pin[(size_t)tt * DI], wv[k], a);
            }
            h[j] = siluf(a);
        } else h[j] = 0.f;
    }
    float xm3 = (t0 - 3 >= 0) ? pin[(size_t)(t0 - 3) * DI] : 0.f;
    float xm2 = (t0 - 2 >= 0) ? pin[(size_t)(t0 - 2) * DI] : 0.f;
    float xm1 = (t0 - 1 >= 0) ? pin[(size_t)(t0 - 1) * DI] : 0.f;

    #pragma unroll
    for (int t = t0; t < t0 + CCHUNK; t++) {
        float xt = pin[(size_t)t * DI];
        float v1 = bb1;
        v1 = fmaf(wa0, xm3, v1); v1 = fmaf(wa1, xm2, v1);
        v1 = fmaf(wa2, xm1, v1); v1 = fmaf(wa3, xt,  v1);
        float s = siluf(v1);
        float v2 = bb2;
        v2 = fmaf(wb0, h[0], v2); v2 = fmaf(wb1, h[1], v2);
        v2 = fmaf(wb2, h[2], v2); v2 = fmaf(wb3, s,    v2);
        pout[(size_t)t * DI] = siluf(v2);
        xm3 = xm2; xm2 = xm1; xm1 = xt;
        h[0] = h[1]; h[1] = h[2]; h[2] = s;
    }
}

// ---------------- x_proj weight transpose: W[l][33][2048] -> Wt[l][2048][34] ----------------
__global__ void wt_transpose(const float* __restrict__ W, float* __restrict__ Wt)
{
    int idx = blockIdx.x * blockDim.x + threadIdx.x;
    if (idx >= NLAYER * 33 * DI) return;
    int k = idx % DI;
    int p = (idx / DI) % 33;
    int l = idx / (DI * 33);
    Wt[((size_t)l * DI + k) * 34 + p] = W[idx];
}

// ---------------- x_proj: block caches 8 rows in smem, lane-per-p ----------------
__global__ void xproj_t(const float* __restrict__ xi, const float* __restrict__ Wt,
                        float* __restrict__ proj)
{
    extern __shared__ float rb[];              // 8 * 2048 floats
    const int w = threadIdx.x >> 5, lane = threadIdx.x & 31;
    const int row0 = blockIdx.x * 8;

    const float4* src = reinterpret_cast<const float4*>(xi + (size_t)row0 * DI);
    float4* dst = reinterpret_cast<float4*>(rb);
    #pragma unroll
    for (int i = 0; i < 16; i++) dst[threadIdx.x + i * 256] = src[threadIdx.x + i * 256];
    __syncthreads();

    const float* r = rb + w * DI;
    float acc = 0.f, acc2 = 0.f;
    #pragma unroll 4
    for (int k = 0; k < DI; k++) {
        float xv = r[k];
        acc  = fmaf(xv, __ldg(&Wt[(size_t)k * 34 + lane]), acc);
        acc2 = fmaf(xv, __ldg(&Wt[(size_t)k * 34 + 32]),   acc2);
    }
    int row = row0 + w;
    proj[(size_t)row * 33 + lane] = acc;       // p = 0..31
    if (lane == 0) proj[(size_t)row * 33 + 32] = acc2;
}

// ---------------- selective scan: 8 threads/channel, prefetched ----------------
__global__ void scan_kernel(const float* __restrict__ xi, const float* __restrict__ proj,
                            const float* __restrict__ dtw, const float* __restrict__ dtb,
                            const float* __restrict__ Dv, float* __restrict__ y)
{
    int t = blockIdx.x * blockDim.x + threadIdx.x;     // BATCH*DI*8
    int sub = t & 7;
    int gid = t >> 3;
    if (gid >= BATCH * DI) return;
    int b = gid / DI, d = gid % DI;
    const float w_dt = dtw[d];
    const float b_dt = dtb[d];
    const float Dd   = Dv[d];
    const float A0 = -(float)(sub * 2 + 1);
    const float A1 = -(float)(sub * 2 + 2);
    float h0 = 0.f, h1 = 0.f;

    const float* prB = proj + (size_t)b * SEQ * 33;
    const float* xB  = xi + (size_t)b * SEQ * DI + d;
    float*       yB  = y  + (size_t)b * SEQ * DI + d;

    float dtraw = __ldg(prB);
    float x     = __ldg(xB);
    float B0 = __ldg(prB + 1 + sub * 2), B1 = __ldg(prB + 2 + sub * 2);
    float C0 = __ldg(prB + 17 + sub * 2), C1 = __ldg(prB + 18 + sub * 2);

    for (int s = 0; s < SEQ; s++) {
        float cdt = dtraw, cx = x, cB0 = B0, cB1 = B1, cC0 = C0, cC1 = C1;
        if (s + 1 < SEQ) {
            const float* pn = prB + (size_t)(s + 1) * 33;
            dtraw = __ldg(pn);
            x     = __ldg(xB + (size_t)(s + 1) * DI);
            B0 = __ldg(pn + 1 + sub * 2);  B1 = __ldg(pn + 2 + sub * 2);
            C0 = __ldg(pn + 17 + sub * 2); C1 = __ldg(pn + 18 + sub * 2);
        }
        float z = fmaf(cdt, w_dt, b_dt);
        float dt = (z > 20.f) ? z : log1pf(expf(z));
        float dtx = dt * cx;
        float t0 = fmaf(h0, A0, dtx * cB0); h0 = fmaf(dt, t0, h0);
        float t1 = fmaf(h1, A1, dtx * cB1); h1 = fmaf(dt, t1, h1);
        float yp = h0 * cC0;
        yp = fmaf(h1, cC1, yp);
        yp += __shfl_xor_sync(0xffffffffu, yp, 1);
        yp += __shfl_xor_sync(0xffffffffu, yp, 2);
        yp += __shfl_xor_sync(0xffffffffu, yp, 4);
        if (sub == 0) yB[(size_t)s * DI] = fmaf(cx, Dd, yp);
    }
}

// ---------------- host orchestration ----------------
#define SMEM128 (2 * (128*SKEWF + 128*SKEWF) * 4)
#define SMEM64  (2 * (128*SKEWF +  64*SKEWF) * 4)
#define XPROJ_SMEM (8 * DI * 4)

extern "C" void kernel_launch(void* const* d_in, const int* in_sizes, int n_in,
                              void* d_out, int out_size)
{
    const float* hidden      = (const float*)d_in[0];
    const float* in_norm_g   = (const float*)d_in[1];
    const float* in_norm_b   = (const float*)d_in[2];
    const float* ln_g        = (const float*)d_in[3];
    const float* ln_b        = (const float*)d_in[4];
    const float* in_proj_w   = (const float*)d_in[5];
    const float* conv_w      = (const float*)d_in[6];
    const float* conv_b      = (const float*)d_in[7];
    const float* x_proj_w    = (const float*)d_in[8];
    const float* dt_proj_w   = (const float*)d_in[9];
    const float* dt_proj_b   = (const float*)d_in[10];
    const float* Dv          = (const float*)d_in[11];
    const float* mamba_ln_g  = (const float*)d_in[12];
    const float* mamba_ln_b  = (const float*)d_in[13];
    const float* out_proj_w  = (const float*)d_in[14];
    const float* op1_w       = (const float*)d_in[15];
    const float* op1_b       = (const float*)d_in[16];
    const float* op2_w       = (const float*)d_in[17];
    const float* op2_b       = (const float*)d_in[18];

    float *x, *xn, *res, *xi, *xi2, *pr, *y, *t1, *wt;
    cudaGetSymbolAddress((void**)&x,   g_x);
    cudaGetSymbolAddress((void**)&xn,  g_xn);
    cudaGetSymbolAddress((void**)&res, g_res);
    cudaGetSymbolAddress((void**)&xi,  g_xi);
    cudaGetSymbolAddress((void**)&xi2, g_xi2);
    cudaGetSymbolAddress((void**)&pr,  g_pr);
    cudaGetSymbolAddress((void**)&y,   g_y);
    cudaGetSymbolAddress((void**)&t1,  g_t1);
    cudaGetSymbolAddress((void**)&wt,  g_wt);

    cudaFuncSetAttribute(gemm_mma<5,128>, cudaFuncAttributeMaxDynamicSharedMemorySize, SMEM128);
    cudaFuncSetAttribute(gemm_mma<0,128>, cudaFuncAttributeMaxDynamicSharedMemorySize, SMEM128);
    cudaFuncSetAttribute(gemm_mma<1,64>,  cudaFuncAttributeMaxDynamicSharedMemorySize, SMEM64);
    cudaFuncSetAttribute(gemm_mma<2,64>,  cudaFuncAttributeMaxDynamicSharedMemorySize, SMEM64);
    cudaFuncSetAttribute(gemm_mma<3,64>,  cudaFuncAttributeMaxDynamicSharedMemorySize, SMEM64);
    cudaFuncSetAttribute(xproj_t, cudaFuncAttributeMaxDynamicSharedMemorySize, XPROJ_SMEM);

    // 0: transpose x_proj weights (all layers)
    wt_transpose<<<(NLAYER * 33 * DI + 255) / 256, 256>>>(x_proj_w, wt);
    // 1: x = LN(hidden)
    ln_kernel<false><<<ROWS, 256>>>(hidden, in_norm_g, in_norm_b, nullptr, x, HID);

    for (int l = 0; l < NLAYER; l++) {
        // xn = LN(x)
        ln_kernel<false><<<ROWS, 256>>>(x, ln_g + (size_t)l * HID, ln_b + (size_t)l * HID,
                                        nullptr, xn, HID);
        // in_proj split: xi = silu(xn @ W_x^T)  (2048 x 2048 x 1024)  <-- launch idx 3 (profiled)
        gemm_mma<5,128><<<dim3(DI / 128, ROWS / 128), 256, SMEM128>>>(
            xn, in_proj_w + (size_t)l * 2 * DI * HID, nullptr, nullptr, xi, ROWS, DI, HID);
        // res = xn @ W_res^T
        gemm_mma<0,128><<<dim3(DI / 128, ROWS / 128), 256, SMEM128>>>(
            xn, in_proj_w + (size_t)l * 2 * DI * HID + (size_t)DI * HID, nullptr, nullptr,
            res, ROWS, DI, HID);
        // fused conv1+silu+conv2+silu : xi -> xi2
        conv2_kernel<<<(BATCH * DI * (SEQ / CCHUNK)) / 256, 256>>>(
            xi,
            conv_w + (size_t)(l * 2 + 0) * DI * KCONV, conv_b + (size_t)(l * 2 + 0) * DI,
            conv_w + (size_t)(l * 2 + 1) * DI * KCONV, conv_b + (size_t)(l * 2 + 1) * DI,
            xi2);
        // proj = x_inner @ x_proj_w^T  (2048 x 33)
        xproj_t<<<ROWS / 8, 256, XPROJ_SMEM>>>(xi2, wt + (size_t)l * DI * 34, pr);
        // selective scan -> y (+ x_inner * D)
        scan_kernel<<<(BATCH * DI * 8) / 128, 128>>>(
            xi2, pr, dt_proj_w + (size_t)l * DI, dt_proj_b + (size_t)l * DI,
            Dv + (size_t)l * DI, y);
        // y = LN(y) * sigmoid(res)
        ln_kernel<true><<<ROWS, 256>>>(y, mamba_ln_g + (size_t)l * DI, mamba_ln_b + (size_t)l * DI,
                                       res, y, DI);
        // x = x + y @ out_proj_w^T  (2048 x 1024 x 2048)
        gemm_mma<1,64><<<dim3(HID / 64, ROWS / 128), 256, SMEM64>>>(
            y, out_proj_w + (size_t)l * HID * DI, nullptr, x, x, ROWS, HID, DI);
    }

    // t1 = gelu(x @ op1_w^T + op1_b)
    gemm_mma<2,64><<<dim3(HID / 64, ROWS / 128), 256, SMEM64>>>(
        x, op1_w, op1_b, nullptr, t1, ROWS, HID, HID);
    // out = t1 @ op2_w^T + op2_b + hidden
    gemm_mma<3,64><<<dim3(HID / 64, ROWS / 128), 256, SMEM64>>>(
        t1, op2_w, op2_b, (float*)hidden, (float*)d_out, ROWS, HID, HID);
}

// round 7
// speedup vs baseline: 2.7363x; 1.4497x over previous
#include <cuda_runtime.h>
#include <math.h>
#include <stdint.h>

#define BATCH 2
#define SEQ   1024
#define HID   1024
#define DI    2048
#define NST   16
#define KCONV 4
#define NLAYER 4
#define ROWS  (BATCH*SEQ)      // 2048
#define LN_EPS 1e-5f

// ---------------- scratch (device globals; no allocation) ----------------
__device__ float g_x  [ROWS*HID];
__device__ float g_xn [ROWS*HID];
__device__ float g_res[ROWS*DI];
__device__ float g_xi [ROWS*DI];
__device__ float g_xi2[ROWS*DI];
__device__ float g_pr [ROWS*64];        // padded proj (stride 64)
__device__ float g_y  [ROWS*DI];
__device__ float g_t1 [ROWS*HID];
__device__ float g_wp [NLAYER*64*DI];   // zero-padded x_proj weights (64 x 2048 per layer)

// ---------------- helpers ----------------
__device__ __forceinline__ float siluf(float v) { return v / (1.f + expf(-v)); }
__device__ __forceinline__ float sigmoidf_(float v) { return 1.f / (1.f + expf(-v)); }
__device__ __forceinline__ float geluf(float v) { return 0.5f * v * (1.f + erff(v * 0.70710678118654752f)); }
__device__ __forceinline__ uint32_t to_tf32u(float x) {
    uint32_t u;
    asm("cvt.rna.tf32.f32 %0, %1;" : "=r"(u) : "f"(x));
    return u;
}
__device__ __forceinline__ uint32_t smem_u32(const void* p) {
    uint32_t a;
    asm("{ .reg .u64 t; cvta.to.shared.u64 t, %1; cvt.u32.u64 %0, t; }" : "=r"(a) : "l"(p));
    return a;
}
__device__ __forceinline__ void cp16(uint32_t d, const void* g) {
    asm volatile("cp.async.cg.shared.global [%0], [%1], 16;" :: "r"(d), "l"(g));
}

// ---------------- LayerNorm (optional sigmoid-gate epilogue) ----------------
template<bool GATE>
__global__ void ln_kernel(const float* __restrict__ in,
                          const float* __restrict__ g,
                          const float* __restrict__ b,
                          const float* __restrict__ gate,
                          float* __restrict__ out, int cols)
{
    __shared__ float buf[2048];
    __shared__ float red[8];
    __shared__ float s_mu, s_rstd;
    const int row = blockIdx.x;
    const int tid = threadIdx.x;
    const float* pin = in + (size_t)row * cols;

    float s = 0.f;
    for (int c = tid; c < cols; c += 256) { float v = pin[c]; buf[c] = v; s += v; }
    #pragma unroll
    for (int o = 16; o; o >>= 1) s += __shfl_xor_sync(0xffffffffu, s, o);
    if ((tid & 31) == 0) red[tid >> 5] = s;
    __syncthreads();
    if (tid == 0) {
        float t = 0.f;
        #pragma unroll
        for (int i = 0; i < 8; i++) t += red[i];
        s_mu = t / (float)cols;
    }
    __syncthreads();
    const float mu = s_mu;
    float v2 = 0.f;
    for (int c = tid; c < cols; c += 256) { float xc = buf[c] - mu; v2 += xc * xc; }
    #pragma unroll
    for (int o = 16; o; o >>= 1) v2 += __shfl_xor_sync(0xffffffffu, v2, o);
    __syncthreads();
    if ((tid & 31) == 0) red[tid >> 5] = v2;
    __syncthreads();
    if (tid == 0) {
        float t = 0.f;
        #pragma unroll
        for (int i = 0; i < 8; i++) t += red[i];
        s_rstd = 1.f / sqrtf(t / (float)cols + LN_EPS);
    }
    __syncthreads();
    const float rstd = s_rstd;
    for (int c = tid; c < cols; c += 256) {
        float val = (buf[c] - mu) * rstd * g[c] + b[c];
        if (GATE) val *= sigmoidf_(gate[(size_t)row * cols + c]);
        out[(size_t)row * cols + c] = val;
    }
}

// ---------------- tf32 mma.sync GEMM, cp.async double-buffered ----------------
// C = A(MxK) * B(NxK)^T, 128 x TBN tile, BK=32, rna-rounded fragments.
// EPI: 0 plain ; 1 +resid ; 2 gelu(acc+bias) ; 3 acc+bias+resid ; 5 silu(acc)
#define SKEWF 36

template<int EPI, int TBN>
__global__ __launch_bounds__(256, 2)
void gemm_mma(const float* __restrict__ A, const float* __restrict__ Bw,
              const float* __restrict__ bias, float* __restrict__ resid,
              float* __restrict__ C, int M, int N, int K)
{
    constexpr int NT   = TBN / 32;
    constexpr int WNC  = TBN / 4;
    constexpr int ASTG = 128 * SKEWF;
    constexpr int BSTG = TBN * SKEWF;
    constexpr int STG  = ASTG + BSTG;
    extern __shared__ float sm[];

    const int tid  = threadIdx.x;
    const int lane = tid & 31;
    const int w    = tid >> 5;
    const int wm   = w & 1;
    const int wn   = w >> 1;
    const int m0 = blockIdx.y * 128;
    const int n0 = blockIdx.x * TBN;
    const int lq = lane >> 2;
    const int lr = lane & 3;

    float acc[4][NT][4];
    #pragma unroll
    for (int i = 0; i < 4; i++)
        #pragma unroll
        for (int j = 0; j < NT; j++)
            #pragma unroll
            for (int r = 0; r < 4; r++) acc[i][j][r] = 0.f;

    const int NC = K >> 5;

    auto load_stage = [&](int s, int k0) {
        float* dA = sm + s * STG;
        float* dB = dA + ASTG;
        #pragma unroll
        for (int i = 0; i < 4; i++) {
            int slot = tid + i * 256;
            int row = slot >> 3, c4 = (slot & 7) * 4;
            cp16(smem_u32(dA + row * SKEWF + c4), A + (size_t)(m0 + row) * K + k0 + c4);
        }
        #pragma unroll
        for (int i = 0; i < TBN * 8 / 256; i++) {
            int slot = tid + i * 256;
            int row = slot >> 3, c4 = (slot & 7) * 4;
            cp16(smem_u32(dB + row * SKEWF + c4), Bw + (size_t)(n0 + row) * K + k0 + c4);
        }
        asm volatile("cp.async.commit_group;" ::: "memory");
    };

    load_stage(0, 0);

    for (int c = 0; c < NC; c++) {
        const int s = c & 1;
        if (c + 1 < NC) {
            load_stage(s ^ 1, (c + 1) * 32);
            asm volatile("cp.async.wait_group 1;" ::: "memory");
        } else {
            asm volatile("cp.async.wait_group 0;" ::: "memory");
        }
        __syncthreads();

        const float* sA = sm + s * STG;
        const float* sB = sA + ASTG;
        #pragma unroll
        for (int kk = 0; kk < 32; kk += 8) {
            uint32_t afr[4][4], bfr[NT][2];
            #pragma unroll
            for (int mt = 0; mt < 4; mt++) {
                int r = wm * 64 + mt * 16 + lq;
                afr[mt][0] = to_tf32u(sA[(r    ) * SKEWF + kk     + lr]);
                afr[mt][1] = to_tf32u(sA[(r + 8) * SKEWF + kk     + lr]);
                afr[mt][2] = to_tf32u(sA[(r    ) * SKEWF + kk + 4 + lr]);
                afr[mt][3] = to_tf32u(sA[(r + 8) * SKEWF + kk + 4 + lr]);
            }
            #pragma unroll
            for (int nt = 0; nt < NT; nt++) {
                int rn = wn * WNC + nt * 8 + lq;
                bfr[nt][0] = to_tf32u(sB[rn * SKEWF + kk     + lr]);
                bfr[nt][1] = to_tf32u(sB[rn * SKEWF + kk + 4 + lr]);
            }
            #pragma unroll
            for (int mt = 0; mt < 4; mt++)
                #pragma unroll
                for (int nt = 0; nt < NT; nt++) {
                    asm volatile(
                        "mma.sync.aligned.m16n8k8.row.col.f32.tf32.tf32.f32 "
                        "{%0,%1,%2,%3}, {%4,%5,%6,%7}, {%8,%9}, {%0,%1,%2,%3};"
                        : "+f"(acc[mt][nt][0]), "+f"(acc[mt][nt][1]),
                          "+f"(acc[mt][nt][2]), "+f"(acc[mt][nt][3])
                        : "r"(afr[mt][0]), "r"(afr[mt][1]), "r"(afr[mt][2]), "r"(afr[mt][3]),
                          "r"(bfr[nt][0]), "r"(bfr[nt][1]));
                }
        }
        __syncthreads();
    }

    #pragma unroll
    for (int mt = 0; mt < 4; mt++) {
        #pragma unroll
        for (int nt = 0; nt < NT; nt++) {
            int r0 = m0 + wm * 64 + mt * 16 + lq;
            int cc = n0 + wn * WNC + nt * 8 + lr * 2;
            #pragma unroll
            for (int half = 0; half < 2; half++) {
                int m = r0 + half * 8;
                float v0 = acc[mt][nt][half * 2 + 0];
                float v1 = acc[mt][nt][half * 2 + 1];
                if (EPI == 0) {
                    *reinterpret_cast<float2*>(&C[(size_t)m * N + cc]) = make_float2(v0, v1);
                } else if (EPI == 1) {
                    float2 rr = *reinterpret_cast<const float2*>(&resid[(size_t)m * N + cc]);
                    *reinterpret_cast<float2*>(&C[(size_t)m * N + cc]) = make_float2(v0 + rr.x, v1 + rr.y);
                } else if (EPI == 2) {
                    *reinterpret_cast<float2*>(&C[(size_t)m * N + cc]) =
                        make_float2(geluf(v0 + bias[cc]), geluf(v1 + bias[cc + 1]));
                } else if (EPI == 3) {
                    float2 rr = *reinterpret_cast<const float2*>(&resid[(size_t)m * N + cc]);
                    *reinterpret_cast<float2*>(&C[(size_t)m * N + cc]) =
                        make_float2(v0 + bias[cc] + rr.x, v1 + bias[cc + 1] + rr.y);
                } else if (EPI == 5) {
                    *reinterpret_cast<float2*>(&C[(size_t)m * N + cc]) =
                        make_float2(siluf(v0), siluf(v1));
                }
            }
        }
    }
}

// ---------------- fused double causal dwconv (K=4) + silu ----------------
#define CCHUNK 16
__global__ void conv2_kernel(const float* __restrict__ in,
                             const float* __restrict__ w1, const float* __restrict__ b1,
                             const float* __restrict__ w2, const float* __restrict__ b2,
                             float* __restrict__ out)
{
    int idx = blockIdx.x * blockDim.x + threadIdx.x;
    if (idx >= BATCH * DI * (SEQ / CCHUNK)) return;
    int d  = idx % DI;
    int r  = idx / DI;
    int c0 = r % (SEQ / CCHUNK);
    int b  = r / (SEQ / CCHUNK);
    int t0 = c0 * CCHUNK;

    const float wa0 = w1[d*4+0], wa1 = w1[d*4+1], wa2 = w1[d*4+2], wa3 = w1[d*4+3];
    const float wb0 = w2[d*4+0], wb1 = w2[d*4+1], wb2 = w2[d*4+2], wb3 = w2[d*4+3];
    const float bb1 = b1[d], bb2 = b2[d];
    const float* pin  = in  + (size_t)b * SEQ * DI + d;
    float*       pout = out + (size_t)b * SEQ * DI + d;

    float h[3];
    #pragma unroll
    for (int j = 0; j < 3; j++) {
        int t = t0 - 3 + j;
        if (t >= 0) {
            float a = bb1;
            float wv[4] = {wa0, wa1, wa2, wa3};
            #pragma unroll
            for (int k = 0; k < 4; k++) {
                int tt = t - 3 + k;
                if (tt >= 0) a = fmaf(pin[(size_t)tt * DI], wv[k], a);
            }
            h[j] = siluf(a);
        } else h[j] = 0.f;
    }
    float xm3 = (t0 - 3 >= 0) ? pin[(size_t)(t0 - 3) * DI] : 0.f;
    float xm2 = (t0 - 2 >= 0) ? pin[(size_t)(t0 - 2) * DI] : 0.f;
    float xm1 = (t0 - 1 >= 0) ? pin[(size_t)(t0 - 1) * DI] : 0.f;

    #pragma unroll
    for (int t = t0; t < t0 + CCHUNK; t++) {
        float xt = pin[(size_t)t * DI];
        float v1 = bb1;
        v1 = fmaf(wa0, xm3, v1); v1 = fmaf(wa1, xm2, v1);
        v1 = fmaf(wa2, xm1, v1); v1 = fmaf(wa3, xt,  v1);
        float s = siluf(v1);
        float v2 = bb2;
        v2 = fmaf(wb0, h[0], v2); v2 = fmaf(wb1, h[1], v2);
        v2 = fmaf(wb2, h[2], v2); v2 = fmaf(wb3, s,    v2);
        pout[(size_t)t * DI] = siluf(v2);
        xm3 = xm2; xm2 = xm1; xm1 = xt;
        h[0] = h[1]; h[1] = h[2]; h[2] = s;
    }
}

// ---------------- x_proj weight zero-pad: W[l][33][2048] -> Wp[l][64][2048] ----------------
__global__ void wpad_kernel(const float* __restrict__ W, float* __restrict__ Wp)
{
    int idx = blockIdx.x * blockDim.x + threadIdx.x;
    if (idx >= NLAYER * 64 * DI) return;
    int k = idx % DI;
    int p = (idx / DI) % 64;
    int l = idx / (DI * 64);
    Wp[idx] = (p < 33) ? W[((size_t)l * 33 + p) * DI + k] : 0.f;
}

// ---------------- selective scan: smem-staged, double-buffered chunks ----------------
// block: 32 channels x 8 subs. Chunks of 64 timesteps. proj has stride 64 (padded).
#define SCH 64
#define NCHK (SEQ / SCH)
#define SCAN_SMEM ((2*SCH*32 + 2*SCH*64 + SCH*32) * 4)

__global__ __launch_bounds__(256)
void scan_kernel(const float* __restrict__ x, const float* __restrict__ pr,
                 const float* __restrict__ dtw, const float* __restrict__ dtb,
                 const float* __restrict__ Dv, float* __restrict__ y)
{
    extern __shared__ float sm[];
    float* SX = sm;                     // [2][SCH][32]
    float* SP = sm + 2 * SCH * 32;      // [2][SCH][64]
    float* SY = SP + 2 * SCH * 64;      // [SCH][32]

    const int tid = threadIdx.x;
    const int dd  = tid >> 3;
    const int sub = tid & 7;
    const int nblk = DI / 32;
    const int b  = blockIdx.x / nblk;
    const int d0 = (blockIdx.x % nblk) * 32;
    const int d  = d0 + dd;

    const float wdt = dtw[d], bdt = dtb[d], Dd = Dv[d];
    const float A0 = -(float)(sub * 2 + 1);
    const float A1 = -(float)(sub * 2 + 2);
    float h0 = 0.f, h1 = 0.f;

    const float* xg = x + (size_t)b * SEQ * DI + d0;
    const float* pg = pr + (size_t)b * SEQ * 64;
    float*       yg = y + (size_t)b * SEQ * DI + d0;

    auto load_chunk = [&](int buf, int c) {
        int t0 = c * SCH;
        float* dx = SX + buf * SCH * 32;
        float* dp = SP + buf * SCH * 64;
        #pragma unroll
        for (int i = 0; i < 2; i++) {
            int sl = tid + i * 256;
            int t = sl >> 3, ch = sl & 7;
            cp16(smem_u32(dx + t * 32 + ch * 4), xg + (size_t)(t0 + t) * DI + ch * 4);
        }
        #pragma unroll
        for (int i = 0; i < 4; i++) {
            int sl = tid + i * 256;
            int t = sl >> 4, ch = sl & 15;
            cp16(smem_u32(dp + t * 64 + ch * 4), pg + (size_t)(t0 + t) * 64 + ch * 4);
        }
        asm volatile("cp.async.commit_group;" ::: "memory");
    };

    load_chunk(0, 0);
    load_chunk(1, 1);

    for (int c = 0; c < NCHK; c++) {
        const int buf = c & 1;
        if (c + 1 < NCHK) asm volatile("cp.async.wait_group 1;" ::: "memory");
        else              asm volatile("cp.async.wait_group 0;" ::: "memory");
        __syncthreads();

        const float* cx = SX + buf * SCH * 32;
        const float* cp = SP + buf * SCH * 64;
        #pragma unroll 4
        for (int s = 0; s < SCH; s++) {
            float dtraw = cp[s * 64];
            float xv    = cx[s * 32 + dd];
            float B0 = cp[s * 64 + 1 + 2 * sub], B1 = cp[s * 64 + 2 + 2 * sub];
            float C0 = cp[s * 64 + 17 + 2 * sub], C1 = cp[s * 64 + 18 + 2 * sub];
            float z  = fmaf(dtraw, wdt, bdt);
            float dt = (z > 20.f) ? z : log1pf(expf(z));
            float dtx = dt * xv;
            float t0v = fmaf(h0, A0, dtx * B0); h0 = fmaf(dt, t0v, h0);
            float t1v = fmaf(h1, A1, dtx * B1); h1 = fmaf(dt, t1v, h1);
            float yp = fmaf(h1, C1, h0 * C0);
            yp += __shfl_xor_sync(0xffffffffu, yp, 1);
            yp += __shfl_xor_sync(0xffffffffu, yp, 2);
            yp += __shfl_xor_sync(0xffffffffu, yp, 4);
            if (sub == 0) SY[s * 32 + dd] = fmaf(xv, Dd, yp);
        }
        __syncthreads();

        const int t0 = c * SCH;
        #pragma unroll
        for (int i = 0; i < 8; i++) {
            int sl = tid + i * 256;
            int s = sl >> 5, dd2 = sl & 31;
            yg[(size_t)(t0 + s) * DI + dd2] = SY[s * 32 + dd2];
        }
        if (c + 2 < NCHK) load_chunk(buf, c + 2);
    }
}

// ---------------- host orchestration ----------------
#define SMEM128 (2 * (128*SKEWF + 128*SKEWF) * 4)
#define SMEM64  (2 * (128*SKEWF +  64*SKEWF) * 4)

extern "C" void kernel_launch(void* const* d_in, const int* in_sizes, int n_in,
                              void* d_out, int out_size)
{
    const float* hidden      = (const float*)d_in[0];
    const float* in_norm_g   = (const float*)d_in[1];
    const float* in_norm_b   = (const float*)d_in[2];
    const float* ln_g        = (const float*)d_in[3];
    const float* ln_b        = (const float*)d_in[4];
    const float* in_proj_w   = (const float*)d_in[5];
    const float* conv_w      = (const float*)d_in[6];
    const float* conv_b      = (const float*)d_in[7];
    const float* x_proj_w    = (const float*)d_in[8];
    const float* dt_proj_w   = (const float*)d_in[9];
    const float* dt_proj_b   = (const float*)d_in[10];
    const float* Dv          = (const float*)d_in[11];
    const float* mamba_ln_g  = (const float*)d_in[12];
    const float* mamba_ln_b  = (const float*)d_in[13];
    const float* out_proj_w  = (const float*)d_in[14];
    const float* op1_w       = (const float*)d_in[15];
    const float* op1_b       = (const float*)d_in[16];
    const float* op2_w       = (const float*)d_in[17];
    const float* op2_b       = (const float*)d_in[18];

    float *x, *xn, *res, *xi, *xi2, *pr, *y, *t1, *wp;
    cudaGetSymbolAddress((void**)&x,   g_x);
    cudaGetSymbolAddress((void**)&xn,  g_xn);
    cudaGetSymbolAddress((void**)&res, g_res);
    cudaGetSymbolAddress((void**)&xi,  g_xi);
    cudaGetSymbolAddress((void**)&xi2, g_xi2);
    cudaGetSymbolAddress((void**)&pr,  g_pr);
    cudaGetSymbolAddress((void**)&y,   g_y);
    cudaGetSymbolAddress((void**)&t1,  g_t1);
    cudaGetSymbolAddress((void**)&wp,  g_wp);

    cudaFuncSetAttribute(gemm_mma<5,128>, cudaFuncAttributeMaxDynamicSharedMemorySize, SMEM128);
    cudaFuncSetAttribute(gemm_mma<0,128>, cudaFuncAttributeMaxDynamicSharedMemorySize, SMEM128);
    cudaFuncSetAttribute(gemm_mma<0,64>,  cudaFuncAttributeMaxDynamicSharedMemorySize, SMEM64);
    cudaFuncSetAttribute(gemm_mma<1,64>,  cudaFuncAttributeMaxDynamicSharedMemorySize, SMEM64);
    cudaFuncSetAttribute(gemm_mma<2,64>,  cudaFuncAttributeMaxDynamicSharedMemorySize, SMEM64);
    cudaFuncSetAttribute(gemm_mma<3,64>,  cudaFuncAttributeMaxDynamicSharedMemorySize, SMEM64);
    cudaFuncSetAttribute(scan_kernel, cudaFuncAttributeMaxDynamicSharedMemorySize, SCAN_SMEM);

    // 0: zero-pad x_proj weights (all layers)
    wpad_kernel<<<(NLAYER * 64 * DI + 255) / 256, 256>>>(x_proj_w, wp);
    // 1: x = LN(hidden)
    ln_kernel<false><<<ROWS, 256>>>(hidden, in_norm_g, in_norm_b, nullptr, x, HID);

    for (int l = 0; l < NLAYER; l++) {
        // xn = LN(x)
        ln_kernel<false><<<ROWS, 256>>>(x, ln_g + (size_t)l * HID, ln_b + (size_t)l * HID,
                                        nullptr, xn, HID);
        // in_proj split: xi = silu(xn @ W_x^T)
        gemm_mma<5,128><<<dim3(DI / 128, ROWS / 128), 256, SMEM128>>>(
            xn, in_proj_w + (size_t)l * 2 * DI * HID, nullptr, nullptr, xi, ROWS, DI, HID);
        // res = xn @ W_res^T
        gemm_mma<0,128><<<dim3(DI / 128, ROWS / 128), 256, SMEM128>>>(
            xn, in_proj_w + (size_t)l * 2 * DI * HID + (size_t)DI * HID, nullptr, nullptr,
            res, ROWS, DI, HID);
        // fused conv1+silu+conv2+silu : xi -> xi2
        conv2_kernel<<<(BATCH * DI * (SEQ / CCHUNK)) / 256, 256>>>(
            xi,
            conv_w + (size_t)(l * 2 + 0) * DI * KCONV, conv_b + (size_t)(l * 2 + 0) * DI,
            conv_w + (size_t)(l * 2 + 1) * DI * KCONV, conv_b + (size_t)(l * 2 + 1) * DI,
            xi2);
        // proj = x_inner @ Wp^T  (2048 x 64 x 2048, tensor cores; cols 33..63 zero)
        gemm_mma<0,64><<<dim3(1, ROWS / 128), 256, SMEM64>>>(
            xi2, wp + (size_t)l * 64 * DI, nullptr, nullptr, pr, ROWS, 64, DI);
        // selective scan -> y (+ x_inner * D)
        scan_kernel<<<BATCH * (DI / 32), 256, SCAN_SMEM>>>(
            xi2, pr, dt_proj_w + (size_t)l * DI, dt_proj_b + (size_t)l * DI,
            Dv + (size_t)l * DI, y);
        // y = LN(y) * sigmoid(res)
        ln_kernel<true><<<ROWS, 256>>>(y, mamba_ln_g + (size_t)l * DI, mamba_ln_b + (size_t)l * DI,
                                       res, y, DI);
        // x = x + y @ out_proj_w^T
        gemm_mma<1,64><<<dim3(HID / 64, ROWS / 128), 256, SMEM64>>>(
            y, out_proj_w + (size_t)l * HID * DI, nullptr, x, x, ROWS, HID, DI);
    }

    // t1 = gelu(x @ op1_w^T + op1_b)
    gemm_mma<2,64><<<dim3(HID / 64, ROWS / 128), 256, SMEM64>>>(
        x, op1_w, op1_b, nullptr, t1, ROWS, HID, HID);
    // out = t1 @ op2_w^T + op2_b + hidden
    gemm_mma<3,64><<<dim3(HID / 64, ROWS / 128), 256, SMEM64>>>(
        t1, op2_w, op2_b, (float*)hidden, (float*)d_out, ROWS, HID, HID);
}